// round 8
// baseline (speedup 1.0000x reference)
#include <cuda_runtime.h>
#include <cuda_fp16.h>
#include <cstdint>

#define Nn 768
#define Hh 128
#define NNPAIR (768 * 768)          // 589824
#define NBLK_A (NNPAIR / 128)       // 4608 (stat tiles of 128 rows)
#define TILES_PER_BLK 4
#define GRID_A (NBLK_A / TILES_PER_BLK)   // 1152

// ---------------- scratch (__device__ globals; no allocation allowed) -------
__device__ __align__(16) __half g_enew[589824ull * 128];   // 151 MB fp16 z
__device__ float g_partS[NBLK_A * Hh];
__device__ float g_partQ[NBLK_A * Hh];
__device__ float g_a2[Hh];                  // gamma * rsqrt(var+eps) * log2(e)
__device__ float g_c2[Hh];                  // a2 * mu
__device__ float g_vx  [Nn * Hh];           // x @ eV_w^T + eV_b
__device__ float g_ux  [Nn * Hh];           // x @ nU_w^T + nU_b
__device__ float g_vx2 [Nn * Hh];           // x @ nV_w^T + nV_b
__device__ float g_Spart[Nn * 4 * Hh];      // softmax-sum partials (4 j-quarters)
__device__ float g_numpart[Nn * 4 * Hh];    // normalized-gate numerator partials

// ---------------- helpers ----------------------------------------------------
__device__ __forceinline__ uint32_t pack_h2(float x, float y)
{
    __half2 h = __floats2half2_rn(x, y);
    return *reinterpret_cast<uint32_t*>(&h);
}
__device__ __forceinline__ void ldsm_x4(uint32_t addr, uint32_t& r0, uint32_t& r1,
                                        uint32_t& r2, uint32_t& r3)
{
    asm volatile("ldmatrix.sync.aligned.m8n8.x4.shared.b16 {%0,%1,%2,%3}, [%4];"
                 : "=r"(r0), "=r"(r1), "=r"(r2), "=r"(r3) : "r"(addr));
}
__device__ __forceinline__ void ldsm_x2(uint32_t addr, uint32_t& r0, uint32_t& r1)
{
    asm volatile("ldmatrix.sync.aligned.m8n8.x2.shared.b16 {%0,%1}, [%2];"
                 : "=r"(r0), "=r"(r1) : "r"(addr));
}
__device__ __forceinline__ void mma16816(float* d, uint32_t a0, uint32_t a1,
                                         uint32_t a2, uint32_t a3,
                                         uint32_t b0, uint32_t b1)
{
    asm volatile(
        "mma.sync.aligned.m16n8k16.row.col.f32.f16.f16.f32 "
        "{%0,%1,%2,%3}, {%4,%5,%6,%7}, {%8,%9}, {%0,%1,%2,%3};"
        : "+f"(d[0]), "+f"(d[1]), "+f"(d[2]), "+f"(d[3])
        : "r"(a0), "r"(a1), "r"(a2), "r"(a3), "r"(b0), "r"(b1));
}

// ---------------- kernel 0: the three small node linears --------------------
__global__ void k_linears(const float* __restrict__ x,
                          const float* __restrict__ Wv,  const float* __restrict__ bv,
                          const float* __restrict__ Wu,  const float* __restrict__ bu,
                          const float* __restrict__ Wv2, const float* __restrict__ bv2)
{
    __shared__ float xs[Hh];
    __shared__ float Ws[32 * 129];
    int i = blockIdx.x, t = threadIdx.x;
    xs[t] = x[i * Hh + t];

    const float* Wp[3] = {Wv, Wu, Wv2};
    const float* Bp[3] = {bv, bu, bv2};
    float* Op[3] = {g_vx, g_ux, g_vx2};

    int warp = t >> 5, lane = t & 31;
    for (int w = 0; w < 3; w++) {
        float acc = 0.f;
        const float* W = Wp[w];
        for (int kb = 0; kb < 4; kb++) {
            __syncthreads();
            #pragma unroll
            for (int m = 0; m < 32; m++) {
                int h = m * 4 + warp;
                Ws[lane * 129 + h] = W[h * Hh + kb * 32 + lane];
            }
            __syncthreads();
            #pragma unroll
            for (int kk = 0; kk < 32; kk++)
                acc = fmaf(xs[kb * 32 + kk], Ws[kk * 129 + t], acc);
        }
        Op[w][i * Hh + t] = acc + Bp[w][t];
        __syncthreads();
    }
}

// ---------------- pass A: fp16 HMMA GEMM, 4 tiles/block, pipelined staging ---
// dyn smem: W [128][68] words + A double-buffer 2x[128][68] = 104448 B
extern __shared__ uint32_t dynbuf[];

__global__ void __launch_bounds__(256, 2) k_passA(const float* __restrict__ e,
                                                  const float* __restrict__ W,
                                                  const float* __restrict__ bias)
{
    __shared__ float sS[256], sQ[256];

    int t = threadIdx.x;
    int warp = t >> 5, lane = t & 31;
    int wm = warp & 3;                     // rows wm*32
    int wn = warp >> 2;                    // cols wn*64
    int pblk = blockIdx.x * (128 * TILES_PER_BLK);

    uint32_t* Wwords = dynbuf;             // [128][68]
    uint32_t* Abuf0  = dynbuf + 8704;      // [128][68]
    uint32_t* Abuf1  = dynbuf + 17408;     // [128][68]
    uint32_t Wbase = (uint32_t)__cvta_generic_to_shared(Wwords);
    uint32_t A0base = (uint32_t)__cvta_generic_to_shared(Abuf0);
    uint32_t A1base = (uint32_t)__cvta_generic_to_shared(Abuf1);

    // stage W once per block
    #pragma unroll
    for (int m = 0; m < 16; m++) {
        int idx = m * 256 + t;
        int r = idx >> 5, q = idx & 31;
        float4 v = *(const float4*)&W[(size_t)r * Hh + q * 4];
        *(uint2*)&Wwords[r * 68 + q * 2] = make_uint2(pack_h2(v.x, v.y), pack_h2(v.z, v.w));
    }
    // stage tile 0 into buf0
    #pragma unroll
    for (int m = 0; m < 16; m++) {
        int idx = m * 256 + t;
        int r = idx >> 5, q = idx & 31;
        float4 v = __ldcs((const float4*)&e[(size_t)(pblk + r) * Hh + q * 4]);
        *(uint2*)&Abuf0[r * 68 + q * 2] = make_uint2(pack_h2(v.x, v.y), pack_h2(v.z, v.w));
    }
    __syncthreads();

    int a_r = lane & 15;
    int a_c16 = ((lane >> 4) & 1) * 8;
    int b_r = lane & 7;
    int b_c16 = ((lane >> 3) & 1) * 8;

    for (int tt = 0; tt < TILES_PER_BLK; tt++) {
        int cur = tt & 1;
        uint32_t* Acur = cur ? Abuf1 : Abuf0;
        uint32_t* Anxt = cur ? Abuf0 : Abuf1;
        uint32_t sbase = cur ? A1base : A0base;
        int p0 = pblk + tt * 128;
        int i0 = p0 / Nn;
        int jbase = p0 - i0 * Nn;
        int p1 = p0 + 128;                 // next tile base
        bool do_stage = (tt < TILES_PER_BLK - 1);

        float acc[2][8][4];
        #pragma unroll
        for (int mi = 0; mi < 2; mi++)
            #pragma unroll
            for (int ni = 0; ni < 8; ni++)
                #pragma unroll
                for (int q = 0; q < 4; q++) acc[mi][ni][q] = 0.f;

        // MMA over 8 k-steps; interleave staging of next tile (2 float4/step)
        #pragma unroll 1
        for (int ks = 0; ks < 8; ks++) {
            if (do_stage) {
                #pragma unroll
                for (int m = 0; m < 2; m++) {
                    int idx = ks * 512 + m * 256 + t;
                    int r = idx >> 5, q = idx & 31;
                    float4 v = __ldcs((const float4*)&e[(size_t)(p1 + r) * Hh + q * 4]);
                    *(uint2*)&Anxt[r * 68 + q * 2] =
                        make_uint2(pack_h2(v.x, v.y), pack_h2(v.z, v.w));
                }
            }
            uint32_t bfr[8][2];
            #pragma unroll
            for (int ni = 0; ni < 8; ni++) {
                int brow = wn * 64 + ni * 8 + b_r;
                uint32_t addr = Wbase + (uint32_t)(brow * 272 + (ks * 16 + b_c16) * 2);
                ldsm_x2(addr, bfr[ni][0], bfr[ni][1]);
            }
            #pragma unroll
            for (int mi = 0; mi < 2; mi++) {
                int arow = wm * 32 + mi * 16 + a_r;
                uint32_t addr = sbase + (uint32_t)(arow * 272 + (ks * 16 + a_c16) * 2);
                uint32_t a0, a1, a2, a3;
                ldsm_x4(addr, a0, a1, a2, a3);
                #pragma unroll
                for (int ni = 0; ni < 8; ni++)
                    mma16816(acc[mi][ni], a0, a1, a2, a3, bfr[ni][0], bfr[ni][1]);
            }
        }
        __syncthreads();                   // Acur reads done; Anxt fully staged

        // epilogue: val = (acc + bias)*(vxi + vxj) -> fp16 tile in Acur [128][66]
        uint32_t* Osm = Acur;
        #pragma unroll
        for (int ni = 0; ni < 8; ni++) {
            int col = wn * 64 + ni * 8 + (lane & 3) * 2;
            float2 bb = *(const float2*)&bias[col];
            float2 vi = *(const float2*)&g_vx[i0 * Hh + col];
            #pragma unroll
            for (int mi = 0; mi < 2; mi++) {
                int r1 = wm * 32 + mi * 16 + (lane >> 2);
                int r2 = r1 + 8;
                float2 vj1 = *(const float2*)&g_vx[(jbase + r1) * Hh + col];
                float2 vj2 = *(const float2*)&g_vx[(jbase + r2) * Hh + col];
                float* a = acc[mi][ni];
                float v00 = (a[0] + bb.x) * (vi.x + vj1.x);
                float v01 = (a[1] + bb.y) * (vi.y + vj1.y);
                float v10 = (a[2] + bb.x) * (vi.x + vj2.x);
                float v11 = (a[3] + bb.y) * (vi.y + vj2.y);
                Osm[r1 * 66 + wn * 32 + ni * 4 + (lane & 3)] = pack_h2(v00, v01);
                Osm[r2 * 66 + wn * 32 + ni * 4 + (lane & 3)] = pack_h2(v10, v11);
            }
        }
        __syncthreads();

        // coalesced global write of the fp16 tile (uint2 = 4 halves)
        uint32_t* gout = (uint32_t*)g_enew;
        #pragma unroll
        for (int m = 0; m < 16; m++) {
            int idx = m * 256 + t;
            int r = idx >> 5, w2 = idx & 31;
            uint2 v = *(uint2*)&Osm[r * 66 + w2 * 2];
            *(uint2*)&gout[(size_t)(p0 + r) * 64 + w2 * 2] = v;
        }

        // per-channel partial sums (deterministic fixed order, same as r5)
        {
            int h = t & 127, half = t >> 7;
            float s = 0.f, q = 0.f;
            int wword = h >> 1, hi = h & 1;
            for (int r = half * 64; r < half * 64 + 64; r++) {
                uint32_t w = Osm[r * 66 + wword];
                __half2 h2 = *reinterpret_cast<__half2*>(&w);
                float v = hi ? __high2float(h2) : __low2float(h2);
                s += v;
                q = fmaf(v, v, q);
            }
            sS[t] = s; sQ[t] = q;
        }
        __syncthreads();
        if (t < 128) {
            int tb = blockIdx.x * TILES_PER_BLK + tt;
            g_partS[tb * Hh + t] = sS[t] + sS[t + 128];
            g_partQ[tb * Hh + t] = sQ[t] + sQ[t + 128];
        }
        __syncthreads();                   // Osm reads done before next staging reuses it
    }
}

// ---------------- A2: reduce channel stats -> a2[h], c2[h] (log2e folded) ----
__global__ void k_stats(const float* __restrict__ gamma)
{
    int h = blockIdx.x, t = threadIdx.x;   // 256 threads
    __shared__ float rs[256], rq[256];
    float s = 0.f, q = 0.f;
    for (int b = t; b < NBLK_A; b += 256) {
        s += g_partS[b * Hh + h];
        q += g_partQ[b * Hh + h];
    }
    rs[t] = s; rq[t] = q;
    __syncthreads();
    for (int o = 128; o > 0; o >>= 1) {
        if (t < o) { rs[t] += rs[t + o]; rq[t] += rq[t + o]; }
        __syncthreads();
    }
    if (t == 0) {
        float mu  = rs[0] * (1.0f / (float)NNPAIR);
        float var = rq[0] * (1.0f / (float)NNPAIR) - mu * mu;
        float a2 = gamma[h] * rsqrtf(var + 1e-5f) * 1.4426950408889634f;
        g_a2[h] = a2;
        g_c2[h] = a2 * mu;
    }
}

// ---------------- B1: softmax-sum partials (reverse-i to catch passA L2 tail) -
__global__ void __launch_bounds__(256) k_sum()
{
    int b = blockIdx.x;
    int i = 767 - (b >> 2), qtr = b & 3;
    int tx = threadIdx.x & 15, ty = threadIdx.x >> 4;
    int h8 = tx * 8;
    __shared__ float sred[16 * 132];

    float4 aL = *(const float4*)&g_a2[h8];
    float4 aH = *(const float4*)&g_a2[h8 + 4];
    float4 cL = *(const float4*)&g_c2[h8];
    float4 cH = *(const float4*)&g_c2[h8 + 4];
    const uint4* rp = (const uint4*)(g_enew + (size_t)i * Nn * Hh);

    float s[8];
    #pragma unroll
    for (int u = 0; u < 8; u++) s[u] = 0.f;

    int j0 = qtr * 192 + ty;
    #pragma unroll 4
    for (int m = 0; m < 12; m++) {
        int j = j0 + m * 16;
        uint4 w = rp[j * 16 + tx];                       // evict-normal (k_gate reuses)
        float2 f0 = __half22float2(*reinterpret_cast<__half2*>(&w.x));
        float2 f1 = __half22float2(*reinterpret_cast<__half2*>(&w.y));
        float2 f2 = __half22float2(*reinterpret_cast<__half2*>(&w.z));
        float2 f3 = __half22float2(*reinterpret_cast<__half2*>(&w.w));
        s[0] += exp2f(fmaf(aL.x, f0.x, -cL.x));
        s[1] += exp2f(fmaf(aL.y, f0.y, -cL.y));
        s[2] += exp2f(fmaf(aL.z, f1.x, -cL.z));
        s[3] += exp2f(fmaf(aL.w, f1.y, -cL.w));
        s[4] += exp2f(fmaf(aH.x, f2.x, -cH.x));
        s[5] += exp2f(fmaf(aH.y, f2.y, -cH.y));
        s[6] += exp2f(fmaf(aH.z, f3.x, -cH.z));
        s[7] += exp2f(fmaf(aH.w, f3.y, -cH.w));
    }
    *(float4*)&sred[ty * 132 + h8]     = make_float4(s[0], s[1], s[2], s[3]);
    *(float4*)&sred[ty * 132 + h8 + 4] = make_float4(s[4], s[5], s[6], s[7]);
    __syncthreads();
    if (threadIdx.x < 128) {
        int h = threadIdx.x;
        float acc = 0.f;
        #pragma unroll
        for (int u = 0; u < 16; u++) acc += sred[u * 132 + h];
        g_Spart[(i * 4 + qtr) * Hh + h] = acc;
    }
}

// ---------------- B2: gates + e_next + numerator partials (forward-i) --------
// g = p/S folded into the exponent: g = exp2(a2*z - (c2 + log2 S))
__global__ void __launch_bounds__(256) k_gate(const float* __restrict__ e,
                                              float* __restrict__ eout)
{
    int b = blockIdx.x;
    int i = b >> 2, qtr = b & 3;
    int tx = threadIdx.x & 15, ty = threadIdx.x >> 4;
    int h8 = tx * 8;
    __shared__ float sred[16 * 132];

    float a2[8], c2p[8];
    #pragma unroll
    for (int u = 0; u < 8; u++) {
        int h = h8 + u;
        float S = ((g_Spart[(i * 4 + 0) * Hh + h] + g_Spart[(i * 4 + 1) * Hh + h])
                 + (g_Spart[(i * 4 + 2) * Hh + h] + g_Spart[(i * 4 + 3) * Hh + h]));
        a2[u]  = g_a2[h];
        c2p[u] = g_c2[h] + __log2f(S);
    }

    const uint4*  rp = (const uint4*)(g_enew + (size_t)i * Nn * Hh);
    const float4* ep = (const float4*)(e    + (size_t)i * Nn * Hh);
    float4*       op = (float4*)(eout + (size_t)i * Nn * Hh);

    float wacc[8];
    #pragma unroll
    for (int u = 0; u < 8; u++) wacc[u] = 0.f;

    int j0 = qtr * 192 + ty;
    #pragma unroll 4
    for (int m = 0; m < 12; m++) {
        int j = j0 + m * 16;
        uint4 w = __ldcs(&rp[j * 16 + tx]);              // last use of enew
        float4 evL = __ldcs(&ep[j * 32 + tx * 2]);
        float4 evH = __ldcs(&ep[j * 32 + tx * 2 + 1]);
        float4 vvL = *(const float4*)&g_vx2[j * Hh + h8];
        float4 vvH = *(const float4*)&g_vx2[j * Hh + h8 + 4];
        float2 f0 = __half22float2(*reinterpret_cast<__half2*>(&w.x));
        float2 f1 = __half22float2(*reinterpret_cast<__half2*>(&w.y));
        float2 f2 = __half22float2(*reinterpret_cast<__half2*>(&w.z));
        float2 f3 = __half22float2(*reinterpret_cast<__half2*>(&w.w));
        float g0 = exp2f(fmaf(a2[0], f0.x, -c2p[0]));
        float g1 = exp2f(fmaf(a2[1], f0.y, -c2p[1]));
        float g2 = exp2f(fmaf(a2[2], f1.x, -c2p[2]));
        float g3 = exp2f(fmaf(a2[3], f1.y, -c2p[3]));
        float g4 = exp2f(fmaf(a2[4], f2.x, -c2p[4]));
        float g5 = exp2f(fmaf(a2[5], f2.y, -c2p[5]));
        float g6 = exp2f(fmaf(a2[6], f3.x, -c2p[6]));
        float g7 = exp2f(fmaf(a2[7], f3.y, -c2p[7]));
        float4 oL, oH;
        oL.x = fmaf(g0, evL.x, evL.x);
        oL.y = fmaf(g1, evL.y, evL.y);
        oL.z = fmaf(g2, evL.z, evL.z);
        oL.w = fmaf(g3, evL.w, evL.w);
        oH.x = fmaf(g4, evH.x, evH.x);
        oH.y = fmaf(g5, evH.y, evH.y);
        oH.z = fmaf(g6, evH.z, evH.z);
        oH.w = fmaf(g7, evH.w, evH.w);
        __stcs(&op[j * 32 + tx * 2],     oL);
        __stcs(&op[j * 32 + tx * 2 + 1], oH);
        wacc[0] = fmaf(g0, vvL.x, wacc[0]);
        wacc[1] = fmaf(g1, vvL.y, wacc[1]);
        wacc[2] = fmaf(g2, vvL.z, wacc[2]);
        wacc[3] = fmaf(g3, vvL.w, wacc[3]);
        wacc[4] = fmaf(g4, vvH.x, wacc[4]);
        wacc[5] = fmaf(g5, vvH.y, wacc[5]);
        wacc[6] = fmaf(g6, vvH.z, wacc[6]);
        wacc[7] = fmaf(g7, vvH.w, wacc[7]);
    }
    *(float4*)&sred[ty * 132 + h8]     = make_float4(wacc[0], wacc[1], wacc[2], wacc[3]);
    *(float4*)&sred[ty * 132 + h8 + 4] = make_float4(wacc[4], wacc[5], wacc[6], wacc[7]);
    __syncthreads();
    if (threadIdx.x < 128) {
        int h = threadIdx.x;
        float acc = 0.f;
        #pragma unroll
        for (int u = 0; u < 16; u++) acc += sred[u * 132 + h];
        g_numpart[(i * 4 + qtr) * Hh + h] = acc;   // already normalized: sum(g*vx2)
    }
}

// ---------------- D: node BN + residual --------------------------------------
__global__ void k_node(const float* __restrict__ x,
                       const float* __restrict__ gamma,
                       const float* __restrict__ beta,
                       float* __restrict__ outx)
{
    int h = blockIdx.x, t = threadIdx.x;   // 256 threads
    __shared__ float vbuf[Nn];
    __shared__ float rs[256], rq[256];
    float s = 0.f, q = 0.f;
    for (int i = t; i < Nn; i += 256) {
        float num = ((g_numpart[(i * 4 + 0) * Hh + h] + g_numpart[(i * 4 + 1) * Hh + h])
                   + (g_numpart[(i * 4 + 2) * Hh + h] + g_numpart[(i * 4 + 3) * Hh + h]));
        float v = g_ux[i * Hh + h] + num;   // den = 1 (+1e-20), normalization folded
        vbuf[i] = v;
        s += v;
        q = fmaf(v, v, q);
    }
    rs[t] = s; rq[t] = q;
    __syncthreads();
    for (int o = 128; o > 0; o >>= 1) {
        if (t < o) { rs[t] += rs[t + o]; rq[t] += rq[t + o]; }
        __syncthreads();
    }
    float mu  = rs[0] * (1.0f / (float)Nn);
    float var = rq[0] * (1.0f / (float)Nn) - mu * mu;
    float scg = gamma[h] * rsqrtf(var + 1e-5f);
    float be  = beta[h];
    for (int i = t; i < Nn; i += 256) {
        float bn = fmaf(scg, vbuf[i] - mu, be);
        outx[i * Hh + h] = x[i * Hh + h] + fmaxf(bn, 0.f);
    }
}

// ---------------- launch ------------------------------------------------------
extern "C" void kernel_launch(void* const* d_in, const int* in_sizes, int n_in,
                              void* d_out, int out_size)
{
    const float* x     = (const float*)d_in[0];
    const float* e     = (const float*)d_in[1];
    const float* eU_w  = (const float*)d_in[2];
    const float* eU_b  = (const float*)d_in[3];
    const float* eV_w  = (const float*)d_in[4];
    const float* eV_b  = (const float*)d_in[5];
    const float* nU_w  = (const float*)d_in[6];
    const float* nU_b  = (const float*)d_in[7];
    const float* nV_w  = (const float*)d_in[8];
    const float* nV_b  = (const float*)d_in[9];
    const float* e_gamma = (const float*)d_in[10];
    // d_in[11] = e_beta: constant over the softmax axis -> cancels exactly
    const float* n_gamma = (const float*)d_in[12];
    const float* n_beta  = (const float*)d_in[13];
    (void)in_sizes; (void)n_in; (void)out_size;

    float* out_x = (float*)d_out;               // x_next: [768,128]
    float* out_e = out_x + Nn * Hh;             // e_next: [768,768,128]

    const int PASSA_SMEM = 3 * 8704 * 4;        // 104448 B dynamic
    static bool attr_done = false;
    if (!attr_done) {
        cudaFuncSetAttribute(k_passA, cudaFuncAttributeMaxDynamicSharedMemorySize,
                             PASSA_SMEM);
        attr_done = true;
    }

    k_linears<<<Nn, Hh>>>(x, eV_w, eV_b, nU_w, nU_b, nV_w, nV_b);
    k_passA  <<<GRID_A, 256, PASSA_SMEM>>>(e, eU_w, eU_b);
    k_stats  <<<Hh, 256>>>(e_gamma);
    k_sum    <<<Nn * 4, 256>>>();
    k_gate   <<<Nn * 4, 256>>>(e, out_e);
    k_node   <<<Hh, 256>>>(x, n_gamma, n_beta, out_x);
}

// round 10
// speedup vs baseline: 1.0942x; 1.0942x over previous
#include <cuda_runtime.h>
#include <cuda_fp16.h>
#include <cstdint>

#define Nn 768
#define Hh 128
#define NNPAIR (768 * 768)          // 589824
#define NBLK_A (NNPAIR / 128)       // 4608

// ---------------- scratch (__device__ globals; no allocation allowed) -------
__device__ __align__(16) __half g_enew[589824ull * 128];   // 151 MB fp16 z
__device__ float g_partS[NBLK_A * Hh];
__device__ float g_partQ[NBLK_A * Hh];
__device__ float g_a2[Hh];                  // gamma * rsqrt(var+eps) * log2(e)
__device__ float g_c2[Hh];                  // a2 * mu
__device__ float g_vx  [Nn * Hh];           // x @ eV_w^T + eV_b
__device__ float g_ux  [Nn * Hh];           // x @ nU_w^T + nU_b
__device__ float g_vx2 [Nn * Hh];           // x @ nV_w^T + nV_b
__device__ float g_Spart[Nn * 4 * Hh];      // softmax-sum partials (4 j-quarters)
__device__ float g_numpart[Nn * 4 * Hh];    // normalized-gate numerator partials

// ---------------- helpers ----------------------------------------------------
__device__ __forceinline__ uint32_t pack_h2(float x, float y)
{
    __half2 h = __floats2half2_rn(x, y);
    return *reinterpret_cast<uint32_t*>(&h);
}
__device__ __forceinline__ void ldsm_x4(uint32_t addr, uint32_t& r0, uint32_t& r1,
                                        uint32_t& r2, uint32_t& r3)
{
    asm volatile("ldmatrix.sync.aligned.m8n8.x4.shared.b16 {%0,%1,%2,%3}, [%4];"
                 : "=r"(r0), "=r"(r1), "=r"(r2), "=r"(r3) : "r"(addr));
}
__device__ __forceinline__ void ldsm_x2(uint32_t addr, uint32_t& r0, uint32_t& r1)
{
    asm volatile("ldmatrix.sync.aligned.m8n8.x2.shared.b16 {%0,%1}, [%2];"
                 : "=r"(r0), "=r"(r1) : "r"(addr));
}
__device__ __forceinline__ void mma16816(float* d, uint32_t a0, uint32_t a1,
                                         uint32_t a2, uint32_t a3,
                                         uint32_t b0, uint32_t b1)
{
    asm volatile(
        "mma.sync.aligned.m16n8k16.row.col.f32.f16.f16.f32 "
        "{%0,%1,%2,%3}, {%4,%5,%6,%7}, {%8,%9}, {%0,%1,%2,%3};"
        : "+f"(d[0]), "+f"(d[1]), "+f"(d[2]), "+f"(d[3])
        : "r"(a0), "r"(a1), "r"(a2), "r"(a3), "r"(b0), "r"(b1));
}

// ---------------- kernel 0: one node linear (launched 3x, selector-based) ----
__global__ void k_linear1(const float* __restrict__ x,
                          const float* __restrict__ W, const float* __restrict__ b,
                          int which)
{
    __shared__ float xs[Hh];
    __shared__ float Ws[32 * 129];
    int i = blockIdx.x, t = threadIdx.x;
    xs[t] = x[i * Hh + t];

    // resolve output INSIDE device code (device symbols are not host-passable)
    float* out = (which == 0) ? g_vx : (which == 1) ? g_ux : g_vx2;

    int warp = t >> 5, lane = t & 31;
    float acc = 0.f;
    for (int kb = 0; kb < 4; kb++) {
        __syncthreads();
        #pragma unroll
        for (int m = 0; m < 32; m++) {
            int h = m * 4 + warp;
            Ws[lane * 129 + h] = W[h * Hh + kb * 32 + lane];
        }
        __syncthreads();
        #pragma unroll
        for (int kk = 0; kk < 32; kk++)
            acc = fmaf(xs[kb * 32 + kk], Ws[kk * 129 + t], acc);
    }
    out[i * Hh + t] = acc + b[t];
}

// ---------------- pass A: fp16 HMMA GEMM, single-stage full-tile staging ------
extern __shared__ uint32_t dynbuf[];

__global__ void __launch_bounds__(256, 2) k_passA(const float* __restrict__ e,
                                                  const float* __restrict__ W,
                                                  const float* __restrict__ bias)
{
    __shared__ float sS[256], sQ[256];

    int t = threadIdx.x;
    int warp = t >> 5, lane = t & 31;
    int wm = warp & 3;                     // rows wm*32
    int wn = warp >> 2;                    // cols wn*64
    int p0 = blockIdx.x * 128;
    int i0 = p0 / Nn;                      // constant per block (128 | 768)
    int jbase = p0 - i0 * Nn;

    uint32_t* Awords = dynbuf;             // [128][68] words (pitch 136 halves)
    uint32_t* Wwords = dynbuf + 8704;
    uint32_t sbase = (uint32_t)__cvta_generic_to_shared(Awords);
    uint32_t Wbase = (uint32_t)__cvta_generic_to_shared(Wwords);

    #pragma unroll
    for (int m = 0; m < 16; m++) {
        int idx = m * 256 + t;
        int r = idx >> 5, q = idx & 31;
        float4 v = __ldcs((const float4*)&e[(size_t)(p0 + r) * Hh + q * 4]);
        *(uint2*)&Awords[r * 68 + q * 2] = make_uint2(pack_h2(v.x, v.y), pack_h2(v.z, v.w));
    }
    #pragma unroll
    for (int m = 0; m < 16; m++) {
        int idx = m * 256 + t;
        int r = idx >> 5, q = idx & 31;
        float4 v = *(const float4*)&W[(size_t)r * Hh + q * 4];
        *(uint2*)&Wwords[r * 68 + q * 2] = make_uint2(pack_h2(v.x, v.y), pack_h2(v.z, v.w));
    }
    __syncthreads();

    int a_r = lane & 15;
    int a_c16 = ((lane >> 4) & 1) * 8;
    int b_r = lane & 7;
    int b_c16 = ((lane >> 3) & 1) * 8;

    float acc[2][8][4];
    #pragma unroll
    for (int mi = 0; mi < 2; mi++)
        #pragma unroll
        for (int ni = 0; ni < 8; ni++)
            #pragma unroll
            for (int q = 0; q < 4; q++) acc[mi][ni][q] = 0.f;

    #pragma unroll
    for (int ks = 0; ks < 8; ks++) {
        uint32_t bfr[8][2];
        #pragma unroll
        for (int ni = 0; ni < 8; ni++) {
            int brow = wn * 64 + ni * 8 + b_r;
            uint32_t addr = Wbase + (uint32_t)(brow * 272 + (ks * 16 + b_c16) * 2);
            ldsm_x2(addr, bfr[ni][0], bfr[ni][1]);
        }
        #pragma unroll
        for (int mi = 0; mi < 2; mi++) {
            int arow = wm * 32 + mi * 16 + a_r;
            uint32_t addr = sbase + (uint32_t)(arow * 272 + (ks * 16 + a_c16) * 2);
            uint32_t a0, a1, a2, a3;
            ldsm_x4(addr, a0, a1, a2, a3);
            #pragma unroll
            for (int ni = 0; ni < 8; ni++)
                mma16816(acc[mi][ni], a0, a1, a2, a3, bfr[ni][0], bfr[ni][1]);
        }
    }
    __syncthreads();                       // smem reads done; reuse A region as out

    // epilogue: val = (acc + bias)*(vxi + vxj) -> fp16 tile [128][66] words
    uint32_t* Osm = Awords;
    #pragma unroll
    for (int ni = 0; ni < 8; ni++) {
        int col = wn * 64 + ni * 8 + (lane & 3) * 2;
        float2 bb = *(const float2*)&bias[col];
        float2 vi = *(const float2*)&g_vx[i0 * Hh + col];
        #pragma unroll
        for (int mi = 0; mi < 2; mi++) {
            int r1 = wm * 32 + mi * 16 + (lane >> 2);
            int r2 = r1 + 8;
            float2 vj1 = *(const float2*)&g_vx[(jbase + r1) * Hh + col];
            float2 vj2 = *(const float2*)&g_vx[(jbase + r2) * Hh + col];
            float* a = acc[mi][ni];
            float v00 = (a[0] + bb.x) * (vi.x + vj1.x);
            float v01 = (a[1] + bb.y) * (vi.y + vj1.y);
            float v10 = (a[2] + bb.x) * (vi.x + vj2.x);
            float v11 = (a[3] + bb.y) * (vi.y + vj2.y);
            Osm[r1 * 66 + wn * 32 + ni * 4 + (lane & 3)] = pack_h2(v00, v01);
            Osm[r2 * 66 + wn * 32 + ni * 4 + (lane & 3)] = pack_h2(v10, v11);
        }
    }
    __syncthreads();

    // coalesced global write of the fp16 tile (uint2 = 4 halves)
    uint32_t* gout = (uint32_t*)g_enew;
    #pragma unroll
    for (int m = 0; m < 16; m++) {
        int idx = m * 256 + t;
        int r = idx >> 5, w2 = idx & 31;
        uint2 v = *(uint2*)&Osm[r * 66 + w2 * 2];
        *(uint2*)&gout[(size_t)(p0 + r) * 64 + w2 * 2] = v;
    }

    // per-channel partial sums of the rounded tile (deterministic fixed order)
    {
        int h = t & 127, half = t >> 7;
        float s = 0.f, q = 0.f;
        int wword = h >> 1, hi = h & 1;
        for (int r = half * 64; r < half * 64 + 64; r++) {
            uint32_t w = Osm[r * 66 + wword];
            __half2 h2 = *reinterpret_cast<__half2*>(&w);
            float v = hi ? __high2float(h2) : __low2float(h2);
            s += v;
            q = fmaf(v, v, q);
        }
        sS[t] = s; sQ[t] = q;
    }
    __syncthreads();
    if (t < 128) {
        g_partS[blockIdx.x * Hh + t] = sS[t] + sS[t + 128];
        g_partQ[blockIdx.x * Hh + t] = sQ[t] + sQ[t + 128];
    }
}

// ---------------- A2: reduce channel stats -> a2[h], c2[h] (log2e folded) ----
__global__ void k_stats(const float* __restrict__ gamma)
{
    int h = blockIdx.x, t = threadIdx.x;   // 256 threads
    __shared__ float rs[256], rq[256];
    float s = 0.f, q = 0.f;
    for (int b = t; b < NBLK_A; b += 256) {
        s += g_partS[b * Hh + h];
        q += g_partQ[b * Hh + h];
    }
    rs[t] = s; rq[t] = q;
    __syncthreads();
    for (int o = 128; o > 0; o >>= 1) {
        if (t < o) { rs[t] += rs[t + o]; rq[t] += rq[t + o]; }
        __syncthreads();
    }
    if (t == 0) {
        float mu  = rs[0] * (1.0f / (float)NNPAIR);
        float var = rq[0] * (1.0f / (float)NNPAIR) - mu * mu;
        float a2 = gamma[h] * rsqrtf(var + 1e-5f) * 1.4426950408889634f;
        g_a2[h] = a2;
        g_c2[h] = a2 * mu;
    }
}

// ---------------- B1: softmax-sum partials (reverse-i to catch passA L2 tail) -
__global__ void __launch_bounds__(256) k_sum()
{
    int b = blockIdx.x;
    int i = 767 - (b >> 2), qtr = b & 3;
    int tx = threadIdx.x & 15, ty = threadIdx.x >> 4;
    int h8 = tx * 8;
    __shared__ float sred[16 * 132];

    float4 aL = *(const float4*)&g_a2[h8];
    float4 aH = *(const float4*)&g_a2[h8 + 4];
    float4 cL = *(const float4*)&g_c2[h8];
    float4 cH = *(const float4*)&g_c2[h8 + 4];
    const uint4* rp = (const uint4*)(g_enew + (size_t)i * Nn * Hh);

    float s[8];
    #pragma unroll
    for (int u = 0; u < 8; u++) s[u] = 0.f;

    int j0 = qtr * 192 + ty;
    #pragma unroll 4
    for (int m = 0; m < 12; m++) {
        int j = j0 + m * 16;
        uint4 w = rp[j * 16 + tx];                       // evict-normal (k_gate reuses)
        float2 f0 = __half22float2(*reinterpret_cast<__half2*>(&w.x));
        float2 f1 = __half22float2(*reinterpret_cast<__half2*>(&w.y));
        float2 f2 = __half22float2(*reinterpret_cast<__half2*>(&w.z));
        float2 f3 = __half22float2(*reinterpret_cast<__half2*>(&w.w));
        s[0] += exp2f(fmaf(aL.x, f0.x, -cL.x));
        s[1] += exp2f(fmaf(aL.y, f0.y, -cL.y));
        s[2] += exp2f(fmaf(aL.z, f1.x, -cL.z));
        s[3] += exp2f(fmaf(aL.w, f1.y, -cL.w));
        s[4] += exp2f(fmaf(aH.x, f2.x, -cH.x));
        s[5] += exp2f(fmaf(aH.y, f2.y, -cH.y));
        s[6] += exp2f(fmaf(aH.z, f3.x, -cH.z));
        s[7] += exp2f(fmaf(aH.w, f3.y, -cH.w));
    }
    *(float4*)&sred[ty * 132 + h8]     = make_float4(s[0], s[1], s[2], s[3]);
    *(float4*)&sred[ty * 132 + h8 + 4] = make_float4(s[4], s[5], s[6], s[7]);
    __syncthreads();
    if (threadIdx.x < 128) {
        int h = threadIdx.x;
        float acc = 0.f;
        #pragma unroll
        for (int u = 0; u < 16; u++) acc += sred[u * 132 + h];
        g_Spart[(i * 4 + qtr) * Hh + h] = acc;
    }
}

// ---------------- B2: gates + e_next + numerator partials (forward-i) --------
// g = p/S folded into the exponent: g = exp2(a2*z - (c2 + log2 S))
__global__ void __launch_bounds__(256) k_gate(const float* __restrict__ e,
                                              float* __restrict__ eout)
{
    int b = blockIdx.x;
    int i = b >> 2, qtr = b & 3;
    int tx = threadIdx.x & 15, ty = threadIdx.x >> 4;
    int h8 = tx * 8;
    __shared__ float sred[16 * 132];

    float a2[8], c2p[8];
    #pragma unroll
    for (int u = 0; u < 8; u++) {
        int h = h8 + u;
        float S = ((g_Spart[(i * 4 + 0) * Hh + h] + g_Spart[(i * 4 + 1) * Hh + h])
                 + (g_Spart[(i * 4 + 2) * Hh + h] + g_Spart[(i * 4 + 3) * Hh + h]));
        a2[u]  = g_a2[h];
        c2p[u] = g_c2[h] + __log2f(S);
    }

    const uint4*  rp = (const uint4*)(g_enew + (size_t)i * Nn * Hh);
    const float4* ep = (const float4*)(e    + (size_t)i * Nn * Hh);
    float4*       op = (float4*)(eout + (size_t)i * Nn * Hh);

    float wacc[8];
    #pragma unroll
    for (int u = 0; u < 8; u++) wacc[u] = 0.f;

    int j0 = qtr * 192 + ty;
    #pragma unroll 4
    for (int m = 0; m < 12; m++) {
        int j = j0 + m * 16;
        uint4 w = __ldcs(&rp[j * 16 + tx]);              // last use of enew
        float4 evL = __ldcs(&ep[j * 32 + tx * 2]);
        float4 evH = __ldcs(&ep[j * 32 + tx * 2 + 1]);
        float4 vvL = *(const float4*)&g_vx2[j * Hh + h8];
        float4 vvH = *(const float4*)&g_vx2[j * Hh + h8 + 4];
        float2 f0 = __half22float2(*reinterpret_cast<__half2*>(&w.x));
        float2 f1 = __half22float2(*reinterpret_cast<__half2*>(&w.y));
        float2 f2 = __half22float2(*reinterpret_cast<__half2*>(&w.z));
        float2 f3 = __half22float2(*reinterpret_cast<__half2*>(&w.w));
        float g0 = exp2f(fmaf(a2[0], f0.x, -c2p[0]));
        float g1 = exp2f(fmaf(a2[1], f0.y, -c2p[1]));
        float g2 = exp2f(fmaf(a2[2], f1.x, -c2p[2]));
        float g3 = exp2f(fmaf(a2[3], f1.y, -c2p[3]));
        float g4 = exp2f(fmaf(a2[4], f2.x, -c2p[4]));
        float g5 = exp2f(fmaf(a2[5], f2.y, -c2p[5]));
        float g6 = exp2f(fmaf(a2[6], f3.x, -c2p[6]));
        float g7 = exp2f(fmaf(a2[7], f3.y, -c2p[7]));
        float4 oL, oH;
        oL.x = fmaf(g0, evL.x, evL.x);
        oL.y = fmaf(g1, evL.y, evL.y);
        oL.z = fmaf(g2, evL.z, evL.z);
        oL.w = fmaf(g3, evL.w, evL.w);
        oH.x = fmaf(g4, evH.x, evH.x);
        oH.y = fmaf(g5, evH.y, evH.y);
        oH.z = fmaf(g6, evH.z, evH.z);
        oH.w = fmaf(g7, evH.w, evH.w);
        __stcs(&op[j * 32 + tx * 2],     oL);
        __stcs(&op[j * 32 + tx * 2 + 1], oH);
        wacc[0] = fmaf(g0, vvL.x, wacc[0]);
        wacc[1] = fmaf(g1, vvL.y, wacc[1]);
        wacc[2] = fmaf(g2, vvL.z, wacc[2]);
        wacc[3] = fmaf(g3, vvL.w, wacc[3]);
        wacc[4] = fmaf(g4, vvH.x, wacc[4]);
        wacc[5] = fmaf(g5, vvH.y, wacc[5]);
        wacc[6] = fmaf(g6, vvH.z, wacc[6]);
        wacc[7] = fmaf(g7, vvH.w, wacc[7]);
    }
    *(float4*)&sred[ty * 132 + h8]     = make_float4(wacc[0], wacc[1], wacc[2], wacc[3]);
    *(float4*)&sred[ty * 132 + h8 + 4] = make_float4(wacc[4], wacc[5], wacc[6], wacc[7]);
    __syncthreads();
    if (threadIdx.x < 128) {
        int h = threadIdx.x;
        float acc = 0.f;
        #pragma unroll
        for (int u = 0; u < 16; u++) acc += sred[u * 132 + h];
        g_numpart[(i * 4 + qtr) * Hh + h] = acc;   // already normalized: sum(g*vx2)
    }
}

// ---------------- D: node BN + residual --------------------------------------
__global__ void k_node(const float* __restrict__ x,
                       const float* __restrict__ gamma,
                       const float* __restrict__ beta,
                       float* __restrict__ outx)
{
    int h = blockIdx.x, t = threadIdx.x;   // 256 threads
    __shared__ float vbuf[Nn];
    __shared__ float rs[256], rq[256];
    float s = 0.f, q = 0.f;
    for (int i = t; i < Nn; i += 256) {
        float num = ((g_numpart[(i * 4 + 0) * Hh + h] + g_numpart[(i * 4 + 1) * Hh + h])
                   + (g_numpart[(i * 4 + 2) * Hh + h] + g_numpart[(i * 4 + 3) * Hh + h]));
        float v = g_ux[i * Hh + h] + num;   // den = 1 (+1e-20), normalization folded
        vbuf[i] = v;
        s += v;
        q = fmaf(v, v, q);
    }
    rs[t] = s; rq[t] = q;
    __syncthreads();
    for (int o = 128; o > 0; o >>= 1) {
        if (t < o) { rs[t] += rs[t + o]; rq[t] += rq[t + o]; }
        __syncthreads();
    }
    float mu  = rs[0] * (1.0f / (float)Nn);
    float var = rq[0] * (1.0f / (float)Nn) - mu * mu;
    float scg = gamma[h] * rsqrtf(var + 1e-5f);
    float be  = beta[h];
    for (int i = t; i < Nn; i += 256) {
        float bn = fmaf(scg, vbuf[i] - mu, be);
        outx[i * Hh + h] = x[i * Hh + h] + fmaxf(bn, 0.f);
    }
}

// ---------------- launch ------------------------------------------------------
extern "C" void kernel_launch(void* const* d_in, const int* in_sizes, int n_in,
                              void* d_out, int out_size)
{
    const float* x     = (const float*)d_in[0];
    const float* e     = (const float*)d_in[1];
    const float* eU_w  = (const float*)d_in[2];
    const float* eU_b  = (const float*)d_in[3];
    const float* eV_w  = (const float*)d_in[4];
    const float* eV_b  = (const float*)d_in[5];
    const float* nU_w  = (const float*)d_in[6];
    const float* nU_b  = (const float*)d_in[7];
    const float* nV_w  = (const float*)d_in[8];
    const float* nV_b  = (const float*)d_in[9];
    const float* e_gamma = (const float*)d_in[10];
    // d_in[11] = e_beta: constant over the softmax axis -> cancels exactly
    const float* n_gamma = (const float*)d_in[12];
    const float* n_beta  = (const float*)d_in[13];
    (void)in_sizes; (void)n_in; (void)out_size;

    float* out_x = (float*)d_out;               // x_next: [768,128]
    float* out_e = out_x + Nn * Hh;             // e_next: [768,768,128]

    const int PASSA_SMEM = 2 * 8704 * 4;        // 69632 B dynamic
    static bool attr_done = false;
    if (!attr_done) {
        cudaFuncSetAttribute(k_passA, cudaFuncAttributeMaxDynamicSharedMemorySize,
                             PASSA_SMEM);
        attr_done = true;
    }

    // Linears split into 3 launches so k_passA lands in the ncu capture slot.
    k_linear1<<<Nn, Hh>>>(x, eV_w, eV_b, 0);
    k_linear1<<<Nn, Hh>>>(x, nU_w, nU_b, 1);
    k_linear1<<<Nn, Hh>>>(x, nV_w, nV_b, 2);
    k_passA  <<<NBLK_A, 256, PASSA_SMEM>>>(e, eU_w, eU_b);
    k_stats  <<<Hh, 256>>>(e_gamma);
    k_sum    <<<Nn * 4, 256>>>();
    k_gate   <<<Nn * 4, 256>>>(e, out_e);
    k_node   <<<Hh, 256>>>(x, n_gamma, n_beta, out_x);
}

// round 11
// speedup vs baseline: 1.1177x; 1.0215x over previous
#include <cuda_runtime.h>
#include <cuda_fp16.h>
#include <cstdint>

#define Nn 768
#define Hh 128
#define NNPAIR (768 * 768)          // 589824
#define NBLK_A (NNPAIR / 128)       // 4608

// ---------------- scratch (__device__ globals; no allocation allowed) -------
__device__ __align__(16) __half g_enew[589824ull * 128];   // 151 MB fp16 z
__device__ float g_partS[NBLK_A * Hh];
__device__ float g_partQ[NBLK_A * Hh];
__device__ float g_a2[Hh];                  // gamma * rsqrt(var+eps) * log2(e)
__device__ float g_c2[Hh];                  // a2 * mu
__device__ float g_vx  [Nn * Hh];           // x @ eV_w^T + eV_b
__device__ float g_ux  [Nn * Hh];           // x @ nU_w^T + nU_b
__device__ float g_vx2 [Nn * Hh];           // x @ nV_w^T + nV_b
__device__ float g_Spart[Nn * 4 * Hh];      // softmax-sum partials (4 j-quarters)
__device__ float g_numpart[Nn * 4 * Hh];    // normalized-gate numerator partials

// ---------------- helpers ----------------------------------------------------
__device__ __forceinline__ uint32_t pack_h2(float x, float y)
{
    __half2 h = __floats2half2_rn(x, y);
    return *reinterpret_cast<uint32_t*>(&h);
}
__device__ __forceinline__ void ldsm_x4(uint32_t addr, uint32_t& r0, uint32_t& r1,
                                        uint32_t& r2, uint32_t& r3)
{
    asm volatile("ldmatrix.sync.aligned.m8n8.x4.shared.b16 {%0,%1,%2,%3}, [%4];"
                 : "=r"(r0), "=r"(r1), "=r"(r2), "=r"(r3) : "r"(addr));
}
__device__ __forceinline__ void ldsm_x2(uint32_t addr, uint32_t& r0, uint32_t& r1)
{
    asm volatile("ldmatrix.sync.aligned.m8n8.x2.shared.b16 {%0,%1}, [%2];"
                 : "=r"(r0), "=r"(r1) : "r"(addr));
}
__device__ __forceinline__ void stsm_x2(uint32_t addr, uint32_t v0, uint32_t v1)
{
    asm volatile("stmatrix.sync.aligned.m8n8.x2.shared.b16 [%0], {%1,%2};"
                 :: "r"(addr), "r"(v0), "r"(v1) : "memory");
}
__device__ __forceinline__ void mma16816(float* d, uint32_t a0, uint32_t a1,
                                         uint32_t a2, uint32_t a3,
                                         uint32_t b0, uint32_t b1)
{
    asm volatile(
        "mma.sync.aligned.m16n8k16.row.col.f32.f16.f16.f32 "
        "{%0,%1,%2,%3}, {%4,%5,%6,%7}, {%8,%9}, {%0,%1,%2,%3};"
        : "+f"(d[0]), "+f"(d[1]), "+f"(d[2]), "+f"(d[3])
        : "r"(a0), "r"(a1), "r"(a2), "r"(a3), "r"(b0), "r"(b1));
}

// ---------------- kernel 0: one node linear (launched 3x, selector-based) ----
__global__ void k_linear1(const float* __restrict__ x,
                          const float* __restrict__ W, const float* __restrict__ b,
                          int which)
{
    __shared__ float xs[Hh];
    __shared__ float Ws[32 * 129];
    int i = blockIdx.x, t = threadIdx.x;
    xs[t] = x[i * Hh + t];

    float* out = (which == 0) ? g_vx : (which == 1) ? g_ux : g_vx2;

    int warp = t >> 5, lane = t & 31;
    float acc = 0.f;
    for (int kb = 0; kb < 4; kb++) {
        __syncthreads();
        #pragma unroll
        for (int m = 0; m < 32; m++) {
            int h = m * 4 + warp;
            Ws[lane * 129 + h] = W[h * Hh + kb * 32 + lane];
        }
        __syncthreads();
        #pragma unroll
        for (int kk = 0; kk < 32; kk++)
            acc = fmaf(xs[kb * 32 + kk], Ws[kk * 129 + t], acc);
    }
    out[i * Hh + t] = acc + b[t];
}

// ---------------- pass A: fp16 HMMA GEMM; reg/shuffle stats; STSM epilogue ---
extern __shared__ uint32_t dynbuf[];

__global__ void __launch_bounds__(256, 2) k_passA(const float* __restrict__ e,
                                                  const float* __restrict__ W,
                                                  const float* __restrict__ bias)
{
    __shared__ float sPS[4 * 128], sPQ[4 * 128];   // per-wm channel partials

    int t = threadIdx.x;
    int warp = t >> 5, lane = t & 31;
    int wm = warp & 3;                     // rows wm*32
    int wn = warp >> 2;                    // cols wn*64
    int p0 = blockIdx.x * 128;
    int i0 = p0 / Nn;                      // constant per block (128 | 768)
    int jbase = p0 - i0 * Nn;

    uint32_t* Awords = dynbuf;             // [128][68] words (pitch 136 halves)
    uint32_t* Wwords = dynbuf + 8704;
    uint32_t sbase = (uint32_t)__cvta_generic_to_shared(Awords);
    uint32_t Wbase = (uint32_t)__cvta_generic_to_shared(Wwords);

    #pragma unroll
    for (int m = 0; m < 16; m++) {
        int idx = m * 256 + t;
        int r = idx >> 5, q = idx & 31;
        float4 v = __ldcs((const float4*)&e[(size_t)(p0 + r) * Hh + q * 4]);
        *(uint2*)&Awords[r * 68 + q * 2] = make_uint2(pack_h2(v.x, v.y), pack_h2(v.z, v.w));
    }
    #pragma unroll
    for (int m = 0; m < 16; m++) {
        int idx = m * 256 + t;
        int r = idx >> 5, q = idx & 31;
        float4 v = *(const float4*)&W[(size_t)r * Hh + q * 4];
        *(uint2*)&Wwords[r * 68 + q * 2] = make_uint2(pack_h2(v.x, v.y), pack_h2(v.z, v.w));
    }
    __syncthreads();

    int a_r = lane & 15;
    int a_c16 = ((lane >> 4) & 1) * 8;
    int b_r = lane & 7;
    int b_c16 = ((lane >> 3) & 1) * 8;

    float acc[2][8][4];
    #pragma unroll
    for (int mi = 0; mi < 2; mi++)
        #pragma unroll
        for (int ni = 0; ni < 8; ni++)
            #pragma unroll
            for (int q = 0; q < 4; q++) acc[mi][ni][q] = 0.f;

    #pragma unroll
    for (int ks = 0; ks < 8; ks++) {
        uint32_t bfr[8][2];
        #pragma unroll
        for (int ni = 0; ni < 8; ni++) {
            int brow = wn * 64 + ni * 8 + b_r;
            uint32_t addr = Wbase + (uint32_t)(brow * 272 + (ks * 16 + b_c16) * 2);
            ldsm_x2(addr, bfr[ni][0], bfr[ni][1]);
        }
        #pragma unroll
        for (int mi = 0; mi < 2; mi++) {
            int arow = wm * 32 + mi * 16 + a_r;
            uint32_t addr = sbase + (uint32_t)(arow * 272 + (ks * 16 + a_c16) * 2);
            uint32_t a0, a1, a2, a3;
            ldsm_x4(addr, a0, a1, a2, a3);
            #pragma unroll
            for (int ni = 0; ni < 8; ni++)
                mma16816(acc[mi][ni], a0, a1, a2, a3, bfr[ni][0], bfr[ni][1]);
        }
    }
    __syncthreads();                       // smem reads done; reuse A region as out

    // epilogue: val = (acc + bias)*(vxi + vxj); STSM tile store; reg/shfl partials
    // out tile pitch = 68 words (272 B): 16B-aligned rows for STSM, conflict-free
    uint32_t* Osm = Awords;
    int strow = wm * 32 + (lane & 7) + ((lane >> 3) & 1) * 8;  // + mi*16 below
    #pragma unroll
    for (int ni = 0; ni < 8; ni++) {
        int col = wn * 64 + ni * 8 + (lane & 3) * 2;
        float2 bb = *(const float2*)&bias[col];
        float2 vi = *(const float2*)&g_vx[i0 * Hh + col];
        float sc0 = 0.f, sc1 = 0.f, qc0 = 0.f, qc1 = 0.f;
        #pragma unroll
        for (int mi = 0; mi < 2; mi++) {
            int r1 = wm * 32 + mi * 16 + (lane >> 2);
            int r2 = r1 + 8;
            float2 vj1 = *(const float2*)&g_vx[(jbase + r1) * Hh + col];
            float2 vj2 = *(const float2*)&g_vx[(jbase + r2) * Hh + col];
            float* a = acc[mi][ni];
            float v00 = (a[0] + bb.x) * (vi.x + vj1.x);
            float v01 = (a[1] + bb.y) * (vi.y + vj1.y);
            float v10 = (a[2] + bb.x) * (vi.x + vj2.x);
            float v11 = (a[3] + bb.y) * (vi.y + vj2.y);
            uint32_t zA = pack_h2(v00, v01);
            uint32_t zB = pack_h2(v10, v11);
            float2 za = __half22float2(*reinterpret_cast<__half2*>(&zA));
            float2 zb = __half22float2(*reinterpret_cast<__half2*>(&zB));
            sc0 += za.x + zb.x;
            sc1 += za.y + zb.y;
            qc0 += za.x * za.x + zb.x * zb.x;
            qc1 += za.y * za.y + zb.y * zb.y;
            uint32_t saddr = sbase +
                (uint32_t)(((strow + mi * 16) * 68 + wn * 32 + ni * 4) * 4);
            stsm_x2(saddr, zA, zB);
        }
        // deterministic xor-tree over the 8 row-lane groups
        #pragma unroll
        for (int o = 4; o <= 16; o <<= 1) {
            sc0 += __shfl_xor_sync(0xffffffffu, sc0, o);
            sc1 += __shfl_xor_sync(0xffffffffu, sc1, o);
            qc0 += __shfl_xor_sync(0xffffffffu, qc0, o);
            qc1 += __shfl_xor_sync(0xffffffffu, qc1, o);
        }
        if (lane < 4) {
            sPS[wm * 128 + col]     = sc0;
            sPS[wm * 128 + col + 1] = sc1;
            sPQ[wm * 128 + col]     = qc0;
            sPQ[wm * 128 + col + 1] = qc1;
        }
    }
    __syncthreads();

    // coalesced STG.128 global write: 128 rows x 16 uint4; 8 per thread
    uint32_t* gout = (uint32_t*)g_enew;
    #pragma unroll
    for (int m = 0; m < 8; m++) {
        int idx = m * 256 + t;
        int r = idx >> 4, w4 = idx & 15;
        uint4 v = *(uint4*)&Osm[r * 68 + w4 * 4];
        *(uint4*)&gout[(size_t)(p0 + r) * 64 + w4 * 4] = v;
    }

    // final per-channel partials (4 wm slices, fixed order)
    if (t < 128) {
        float s = (sPS[t] + sPS[128 + t]) + (sPS[256 + t] + sPS[384 + t]);
        float q = (sPQ[t] + sPQ[128 + t]) + (sPQ[256 + t] + sPQ[384 + t]);
        g_partS[blockIdx.x * Hh + t] = s;
        g_partQ[blockIdx.x * Hh + t] = q;
    }
}

// ---------------- A2: reduce channel stats -> a2[h], c2[h] (log2e folded) ----
__global__ void k_stats(const float* __restrict__ gamma)
{
    int h = blockIdx.x, t = threadIdx.x;   // 256 threads
    __shared__ float rs[256], rq[256];
    float s = 0.f, q = 0.f;
    for (int b = t; b < NBLK_A; b += 256) {
        s += g_partS[b * Hh + h];
        q += g_partQ[b * Hh + h];
    }
    rs[t] = s; rq[t] = q;
    __syncthreads();
    for (int o = 128; o > 0; o >>= 1) {
        if (t < o) { rs[t] += rs[t + o]; rq[t] += rq[t + o]; }
        __syncthreads();
    }
    if (t == 0) {
        float mu  = rs[0] * (1.0f / (float)NNPAIR);
        float var = rq[0] * (1.0f / (float)NNPAIR) - mu * mu;
        float a2 = gamma[h] * rsqrtf(var + 1e-5f) * 1.4426950408889634f;
        g_a2[h] = a2;
        g_c2[h] = a2 * mu;
    }
}

// ---------------- B1: softmax-sum partials (reverse-i to catch passA L2 tail) -
__global__ void __launch_bounds__(256) k_sum()
{
    int b = blockIdx.x;
    int i = 767 - (b >> 2), qtr = b & 3;
    int tx = threadIdx.x & 15, ty = threadIdx.x >> 4;
    int h8 = tx * 8;
    __shared__ float sred[16 * 132];

    float4 aL = *(const float4*)&g_a2[h8];
    float4 aH = *(const float4*)&g_a2[h8 + 4];
    float4 cL = *(const float4*)&g_c2[h8];
    float4 cH = *(const float4*)&g_c2[h8 + 4];
    const uint4* rp = (const uint4*)(g_enew + (size_t)i * Nn * Hh);

    float s[8];
    #pragma unroll
    for (int u = 0; u < 8; u++) s[u] = 0.f;

    int j0 = qtr * 192 + ty;
    #pragma unroll 4
    for (int m = 0; m < 12; m++) {
        int j = j0 + m * 16;
        uint4 w = rp[j * 16 + tx];                       // evict-normal (k_gate reuses)
        float2 f0 = __half22float2(*reinterpret_cast<__half2*>(&w.x));
        float2 f1 = __half22float2(*reinterpret_cast<__half2*>(&w.y));
        float2 f2 = __half22float2(*reinterpret_cast<__half2*>(&w.z));
        float2 f3 = __half22float2(*reinterpret_cast<__half2*>(&w.w));
        s[0] += exp2f(fmaf(aL.x, f0.x, -cL.x));
        s[1] += exp2f(fmaf(aL.y, f0.y, -cL.y));
        s[2] += exp2f(fmaf(aL.z, f1.x, -cL.z));
        s[3] += exp2f(fmaf(aL.w, f1.y, -cL.w));
        s[4] += exp2f(fmaf(aH.x, f2.x, -cH.x));
        s[5] += exp2f(fmaf(aH.y, f2.y, -cH.y));
        s[6] += exp2f(fmaf(aH.z, f3.x, -cH.z));
        s[7] += exp2f(fmaf(aH.w, f3.y, -cH.w));
    }
    *(float4*)&sred[ty * 132 + h8]     = make_float4(s[0], s[1], s[2], s[3]);
    *(float4*)&sred[ty * 132 + h8 + 4] = make_float4(s[4], s[5], s[6], s[7]);
    __syncthreads();
    if (threadIdx.x < 128) {
        int h = threadIdx.x;
        float acc = 0.f;
        #pragma unroll
        for (int u = 0; u < 16; u++) acc += sred[u * 132 + h];
        g_Spart[(i * 4 + qtr) * Hh + h] = acc;
    }
}

// ---------------- B2: gates + e_next + numerator partials (forward-i) --------
// g = p/S folded into the exponent: g = exp2(a2*z - (c2 + log2 S))
__global__ void __launch_bounds__(256) k_gate(const float* __restrict__ e,
                                              float* __restrict__ eout)
{
    int b = blockIdx.x;
    int i = b >> 2, qtr = b & 3;
    int tx = threadIdx.x & 15, ty = threadIdx.x >> 4;
    int h8 = tx * 8;
    __shared__ float sred[16 * 132];

    float a2[8], c2p[8];
    #pragma unroll
    for (int u = 0; u < 8; u++) {
        int h = h8 + u;
        float S = ((g_Spart[(i * 4 + 0) * Hh + h] + g_Spart[(i * 4 + 1) * Hh + h])
                 + (g_Spart[(i * 4 + 2) * Hh + h] + g_Spart[(i * 4 + 3) * Hh + h]));
        a2[u]  = g_a2[h];
        c2p[u] = g_c2[h] + __log2f(S);
    }

    const uint4*  rp = (const uint4*)(g_enew + (size_t)i * Nn * Hh);
    const float4* ep = (const float4*)(e    + (size_t)i * Nn * Hh);
    float4*       op = (float4*)(eout + (size_t)i * Nn * Hh);

    float wacc[8];
    #pragma unroll
    for (int u = 0; u < 8; u++) wacc[u] = 0.f;

    int j0 = qtr * 192 + ty;
    #pragma unroll 4
    for (int m = 0; m < 12; m++) {
        int j = j0 + m * 16;
        uint4 w = __ldcs(&rp[j * 16 + tx]);              // last use of enew
        float4 evL = __ldcs(&ep[j * 32 + tx * 2]);
        float4 evH = __ldcs(&ep[j * 32 + tx * 2 + 1]);
        float4 vvL = *(const float4*)&g_vx2[j * Hh + h8];
        float4 vvH = *(const float4*)&g_vx2[j * Hh + h8 + 4];
        float2 f0 = __half22float2(*reinterpret_cast<__half2*>(&w.x));
        float2 f1 = __half22float2(*reinterpret_cast<__half2*>(&w.y));
        float2 f2 = __half22float2(*reinterpret_cast<__half2*>(&w.z));
        float2 f3 = __half22float2(*reinterpret_cast<__half2*>(&w.w));
        float g0 = exp2f(fmaf(a2[0], f0.x, -c2p[0]));
        float g1 = exp2f(fmaf(a2[1], f0.y, -c2p[1]));
        float g2 = exp2f(fmaf(a2[2], f1.x, -c2p[2]));
        float g3 = exp2f(fmaf(a2[3], f1.y, -c2p[3]));
        float g4 = exp2f(fmaf(a2[4], f2.x, -c2p[4]));
        float g5 = exp2f(fmaf(a2[5], f2.y, -c2p[5]));
        float g6 = exp2f(fmaf(a2[6], f3.x, -c2p[6]));
        float g7 = exp2f(fmaf(a2[7], f3.y, -c2p[7]));
        float4 oL, oH;
        oL.x = fmaf(g0, evL.x, evL.x);
        oL.y = fmaf(g1, evL.y, evL.y);
        oL.z = fmaf(g2, evL.z, evL.z);
        oL.w = fmaf(g3, evL.w, evL.w);
        oH.x = fmaf(g4, evH.x, evH.x);
        oH.y = fmaf(g5, evH.y, evH.y);
        oH.z = fmaf(g6, evH.z, evH.z);
        oH.w = fmaf(g7, evH.w, evH.w);
        __stcs(&op[j * 32 + tx * 2],     oL);
        __stcs(&op[j * 32 + tx * 2 + 1], oH);
        wacc[0] = fmaf(g0, vvL.x, wacc[0]);
        wacc[1] = fmaf(g1, vvL.y, wacc[1]);
        wacc[2] = fmaf(g2, vvL.z, wacc[2]);
        wacc[3] = fmaf(g3, vvL.w, wacc[3]);
        wacc[4] = fmaf(g4, vvH.x, wacc[4]);
        wacc[5] = fmaf(g5, vvH.y, wacc[5]);
        wacc[6] = fmaf(g6, vvH.z, wacc[6]);
        wacc[7] = fmaf(g7, vvH.w, wacc[7]);
    }
    *(float4*)&sred[ty * 132 + h8]     = make_float4(wacc[0], wacc[1], wacc[2], wacc[3]);
    *(float4*)&sred[ty * 132 + h8 + 4] = make_float4(wacc[4], wacc[5], wacc[6], wacc[7]);
    __syncthreads();
    if (threadIdx.x < 128) {
        int h = threadIdx.x;
        float acc = 0.f;
        #pragma unroll
        for (int u = 0; u < 16; u++) acc += sred[u * 132 + h];
        g_numpart[(i * 4 + qtr) * Hh + h] = acc;   // already normalized: sum(g*vx2)
    }
}

// ---------------- D: node BN + residual --------------------------------------
__global__ void k_node(const float* __restrict__ x,
                       const float* __restrict__ gamma,
                       const float* __restrict__ beta,
                       float* __restrict__ outx)
{
    int h = blockIdx.x, t = threadIdx.x;   // 256 threads
    __shared__ float vbuf[Nn];
    __shared__ float rs[256], rq[256];
    float s = 0.f, q = 0.f;
    for (int i = t; i < Nn; i += 256) {
        float num = ((g_numpart[(i * 4 + 0) * Hh + h] + g_numpart[(i * 4 + 1) * Hh + h])
                   + (g_numpart[(i * 4 + 2) * Hh + h] + g_numpart[(i * 4 + 3) * Hh + h]));
        float v = g_ux[i * Hh + h] + num;   // den = 1 (+1e-20), normalization folded
        vbuf[i] = v;
        s += v;
        q = fmaf(v, v, q);
    }
    rs[t] = s; rq[t] = q;
    __syncthreads();
    for (int o = 128; o > 0; o >>= 1) {
        if (t < o) { rs[t] += rs[t + o]; rq[t] += rq[t + o]; }
        __syncthreads();
    }
    float mu  = rs[0] * (1.0f / (float)Nn);
    float var = rq[0] * (1.0f / (float)Nn) - mu * mu;
    float scg = gamma[h] * rsqrtf(var + 1e-5f);
    float be  = beta[h];
    for (int i = t; i < Nn; i += 256) {
        float bn = fmaf(scg, vbuf[i] - mu, be);
        outx[i * Hh + h] = x[i * Hh + h] + fmaxf(bn, 0.f);
    }
}

// ---------------- launch ------------------------------------------------------
extern "C" void kernel_launch(void* const* d_in, const int* in_sizes, int n_in,
                              void* d_out, int out_size)
{
    const float* x     = (const float*)d_in[0];
    const float* e     = (const float*)d_in[1];
    const float* eU_w  = (const float*)d_in[2];
    const float* eU_b  = (const float*)d_in[3];
    const float* eV_w  = (const float*)d_in[4];
    const float* eV_b  = (const float*)d_in[5];
    const float* nU_w  = (const float*)d_in[6];
    const float* nU_b  = (const float*)d_in[7];
    const float* nV_w  = (const float*)d_in[8];
    const float* nV_b  = (const float*)d_in[9];
    const float* e_gamma = (const float*)d_in[10];
    // d_in[11] = e_beta: constant over the softmax axis -> cancels exactly
    const float* n_gamma = (const float*)d_in[12];
    const float* n_beta  = (const float*)d_in[13];
    (void)in_sizes; (void)n_in; (void)out_size;

    float* out_x = (float*)d_out;               // x_next: [768,128]
    float* out_e = out_x + Nn * Hh;             // e_next: [768,768,128]

    const int PASSA_SMEM = 2 * 8704 * 4;        // 69632 B dynamic
    static bool attr_done = false;
    if (!attr_done) {
        cudaFuncSetAttribute(k_passA, cudaFuncAttributeMaxDynamicSharedMemorySize,
                             PASSA_SMEM);
        attr_done = true;
    }

    // Linears split into 3 launches so k_passA lands in the ncu capture slot.
    k_linear1<<<Nn, Hh>>>(x, eV_w, eV_b, 0);
    k_linear1<<<Nn, Hh>>>(x, nU_w, nU_b, 1);
    k_linear1<<<Nn, Hh>>>(x, nV_w, nV_b, 2);
    k_passA  <<<NBLK_A, 256, PASSA_SMEM>>>(e, eU_w, eU_b);
    k_stats  <<<Hh, 256>>>(e_gamma);
    k_sum    <<<Nn * 4, 256>>>();
    k_gate   <<<Nn * 4, 256>>>(e, out_e);
    k_node   <<<Hh, 256>>>(x, n_gamma, n_beta, out_x);
}

// round 13
// speedup vs baseline: 1.1498x; 1.0287x over previous
#include <cuda_runtime.h>
#include <cuda_fp16.h>
#include <cstdint>

#define Nn 768
#define Hh 128
#define NNPAIR (768 * 768)          // 589824
#define NBLK_A (NNPAIR / 128)       // 4608

// ---------------- scratch (__device__ globals; no allocation allowed) -------
__device__ __align__(16) __half g_enew[589824ull * 128];   // 151 MB fp16 z
__device__ __align__(16) __half g_w16[Hh * Hh];            // eU_w in fp16
__device__ float g_partS[NBLK_A * Hh];
__device__ float g_partQ[NBLK_A * Hh];
__device__ float g_a2[Hh];                  // gamma * rsqrt(var+eps) * log2(e)
__device__ float g_c2[Hh];                  // a2 * mu
__device__ float g_vx  [Nn * Hh];           // x @ eV_w^T + eV_b
__device__ float g_ux  [Nn * Hh];           // x @ nU_w^T + nU_b
__device__ float g_vx2 [Nn * Hh];           // x @ nV_w^T + nV_b
__device__ float g_Spart[Nn * 4 * Hh];      // softmax-sum partials (4 j-quarters)
__device__ float g_numpart[Nn * 4 * Hh];    // normalized-gate numerator partials

// ---------------- helpers ----------------------------------------------------
__device__ __forceinline__ uint32_t pack_h2(float x, float y)
{
    __half2 h = __floats2half2_rn(x, y);
    return *reinterpret_cast<uint32_t*>(&h);
}
__device__ __forceinline__ void ldsm_x4(uint32_t addr, uint32_t& r0, uint32_t& r1,
                                        uint32_t& r2, uint32_t& r3)
{
    asm volatile("ldmatrix.sync.aligned.m8n8.x4.shared.b16 {%0,%1,%2,%3}, [%4];"
                 : "=r"(r0), "=r"(r1), "=r"(r2), "=r"(r3) : "r"(addr));
}
__device__ __forceinline__ void ldsm_x2(uint32_t addr, uint32_t& r0, uint32_t& r1)
{
    asm volatile("ldmatrix.sync.aligned.m8n8.x2.shared.b16 {%0,%1}, [%2];"
                 : "=r"(r0), "=r"(r1) : "r"(addr));
}
__device__ __forceinline__ void stsm_x2(uint32_t addr, uint32_t v0, uint32_t v1)
{
    asm volatile("stmatrix.sync.aligned.m8n8.x2.shared.b16 [%0], {%1,%2};"
                 :: "r"(addr), "r"(v0), "r"(v1) : "memory");
}
__device__ __forceinline__ void mma16816(float* d, uint32_t a0, uint32_t a1,
                                         uint32_t a2, uint32_t a3,
                                         uint32_t b0, uint32_t b1)
{
    asm volatile(
        "mma.sync.aligned.m16n8k16.row.col.f32.f16.f16.f32 "
        "{%0,%1,%2,%3}, {%4,%5,%6,%7}, {%8,%9}, {%0,%1,%2,%3};"
        : "+f"(d[0]), "+f"(d[1]), "+f"(d[2]), "+f"(d[3])
        : "r"(a0), "r"(a1), "r"(a2), "r"(a3), "r"(b0), "r"(b1));
}

// ---------------- kernel 0: one node linear (3x); which==0 also converts W ---
__global__ void k_linear1(const float* __restrict__ x,
                          const float* __restrict__ W, const float* __restrict__ b,
                          const float* __restrict__ Wconv, int which)
{
    __shared__ float xs[Hh];
    __shared__ float Ws[32 * 129];
    int i = blockIdx.x, t = threadIdx.x;
    xs[t] = x[i * Hh + t];

    // fold eU_w fp32->fp16 conversion into the first linear launch
    if (which == 0 && i < Hh)
        g_w16[i * Hh + t] = __float2half_rn(Wconv[i * Hh + t]);

    float* out = (which == 0) ? g_vx : (which == 1) ? g_ux : g_vx2;

    int warp = t >> 5, lane = t & 31;
    float acc = 0.f;
    for (int kb = 0; kb < 4; kb++) {
        __syncthreads();
        #pragma unroll
        for (int m = 0; m < 32; m++) {
            int h = m * 4 + warp;
            Ws[lane * 129 + h] = W[h * Hh + kb * 32 + lane];
        }
        __syncthreads();
        #pragma unroll
        for (int kk = 0; kk < 32; kk++)
            acc = fmaf(xs[kb * 32 + kk], Ws[kk * 129 + t], acc);
    }
    out[i * Hh + t] = acc + b[t];
}

// ---------------- pass A: fp16 HMMA GEMM; W staged from fp16 copy ------------
extern __shared__ uint32_t dynbuf[];

__global__ void __launch_bounds__(256, 2) k_passA(const float* __restrict__ e,
                                                  const float* __restrict__ bias)
{
    __shared__ float sPS[4 * 128], sPQ[4 * 128];   // per-wm channel partials

    int t = threadIdx.x;
    int warp = t >> 5, lane = t & 31;
    int wm = warp & 3;                     // rows wm*32
    int wn = warp >> 2;                    // cols wn*64
    int p0 = blockIdx.x * 128;
    int i0 = p0 / Nn;                      // constant per block (128 | 768)
    int jbase = p0 - i0 * Nn;

    uint32_t* Awords = dynbuf;             // [128][68] words (pitch 272 B)
    uint32_t* Wwords = dynbuf + 8704;
    uint32_t sbase = (uint32_t)__cvta_generic_to_shared(Awords);
    uint32_t Wbase = (uint32_t)__cvta_generic_to_shared(Wwords);

    // stage A (e tile): fp32 -> fp16
    #pragma unroll
    for (int m = 0; m < 16; m++) {
        int idx = m * 256 + t;
        int r = idx >> 5, q = idx & 31;
        float4 v = __ldcs((const float4*)&e[(size_t)(p0 + r) * Hh + q * 4]);
        *(uint2*)&Awords[r * 68 + q * 2] = make_uint2(pack_h2(v.x, v.y), pack_h2(v.z, v.w));
    }
    // stage W: straight fp16 copy (8 uint4 per thread, no conversion)
    #pragma unroll
    for (int m = 0; m < 8; m++) {
        int idx = m * 256 + t;
        int r = idx >> 4, c = idx & 15;
        uint4 v = *(const uint4*)&g_w16[r * Hh + c * 8];
        *(uint4*)&Wwords[r * 68 + c * 4] = v;
    }
    __syncthreads();

    int a_r = lane & 15;
    int a_c16 = ((lane >> 4) & 1) * 8;
    int b_r = lane & 7;
    int b_c16 = ((lane >> 3) & 1) * 8;

    float acc[2][8][4];
    #pragma unroll
    for (int mi = 0; mi < 2; mi++)
        #pragma unroll
        for (int ni = 0; ni < 8; ni++)
            #pragma unroll
            for (int q = 0; q < 4; q++) acc[mi][ni][q] = 0.f;

    #pragma unroll
    for (int ks = 0; ks < 8; ks++) {
        uint32_t bfr[8][2];
        #pragma unroll
        for (int ni = 0; ni < 8; ni++) {
            int brow = wn * 64 + ni * 8 + b_r;
            uint32_t addr = Wbase + (uint32_t)(brow * 272 + (ks * 16 + b_c16) * 2);
            ldsm_x2(addr, bfr[ni][0], bfr[ni][1]);
        }
        #pragma unroll
        for (int mi = 0; mi < 2; mi++) {
            int arow = wm * 32 + mi * 16 + a_r;
            uint32_t addr = sbase + (uint32_t)(arow * 272 + (ks * 16 + a_c16) * 2);
            uint32_t a0, a1, a2, a3;
            ldsm_x4(addr, a0, a1, a2, a3);
            #pragma unroll
            for (int ni = 0; ni < 8; ni++)
                mma16816(acc[mi][ni], a0, a1, a2, a3, bfr[ni][0], bfr[ni][1]);
        }
    }
    __syncthreads();                       // smem reads done; reuse A region as out

    // epilogue: val = (acc + bias)*(vxi + vxj); STSM tile store; reg/shfl partials
    uint32_t* Osm = Awords;
    int strow = wm * 32 + (lane & 7) + ((lane >> 3) & 1) * 8;  // + mi*16 below
    #pragma unroll
    for (int ni = 0; ni < 8; ni++) {
        int col = wn * 64 + ni * 8 + (lane & 3) * 2;
        float2 bb = *(const float2*)&bias[col];
        float2 vi = *(const float2*)&g_vx[i0 * Hh + col];
        float sc0 = 0.f, sc1 = 0.f, qc0 = 0.f, qc1 = 0.f;
        #pragma unroll
        for (int mi = 0; mi < 2; mi++) {
            int r1 = wm * 32 + mi * 16 + (lane >> 2);
            int r2 = r1 + 8;
            float2 vj1 = *(const float2*)&g_vx[(jbase + r1) * Hh + col];
            float2 vj2 = *(const float2*)&g_vx[(jbase + r2) * Hh + col];
            float* a = acc[mi][ni];
            float v00 = (a[0] + bb.x) * (vi.x + vj1.x);
            float v01 = (a[1] + bb.y) * (vi.y + vj1.y);
            float v10 = (a[2] + bb.x) * (vi.x + vj2.x);
            float v11 = (a[3] + bb.y) * (vi.y + vj2.y);
            uint32_t zA = pack_h2(v00, v01);
            uint32_t zB = pack_h2(v10, v11);
            float2 za = __half22float2(*reinterpret_cast<__half2*>(&zA));
            float2 zb = __half22float2(*reinterpret_cast<__half2*>(&zB));
            sc0 += za.x + zb.x;
            sc1 += za.y + zb.y;
            qc0 += za.x * za.x + zb.x * zb.x;
            qc1 += za.y * za.y + zb.y * zb.y;
            uint32_t saddr = sbase +
                (uint32_t)(((strow + mi * 16) * 68 + wn * 32 + ni * 4) * 4);
            stsm_x2(saddr, zA, zB);
        }
        #pragma unroll
        for (int o = 4; o <= 16; o <<= 1) {
            sc0 += __shfl_xor_sync(0xffffffffu, sc0, o);
            sc1 += __shfl_xor_sync(0xffffffffu, sc1, o);
            qc0 += __shfl_xor_sync(0xffffffffu, qc0, o);
            qc1 += __shfl_xor_sync(0xffffffffu, qc1, o);
        }
        if (lane < 4) {
            sPS[wm * 128 + col]     = sc0;
            sPS[wm * 128 + col + 1] = sc1;
            sPQ[wm * 128 + col]     = qc0;
            sPQ[wm * 128 + col + 1] = qc1;
        }
    }
    __syncthreads();

    // coalesced STG.128 global write: 128 rows x 16 uint4; 8 per thread
    uint32_t* gout = (uint32_t*)g_enew;
    #pragma unroll
    for (int m = 0; m < 8; m++) {
        int idx = m * 256 + t;
        int r = idx >> 4, w4 = idx & 15;
        uint4 v = *(uint4*)&Osm[r * 68 + w4 * 4];
        *(uint4*)&gout[(size_t)(p0 + r) * 64 + w4 * 4] = v;
    }

    // final per-channel partials (4 wm slices, fixed order)
    if (t < 128) {
        float s = (sPS[t] + sPS[128 + t]) + (sPS[256 + t] + sPS[384 + t]);
        float q = (sPQ[t] + sPQ[128 + t]) + (sPQ[256 + t] + sPQ[384 + t]);
        g_partS[blockIdx.x * Hh + t] = s;
        g_partQ[blockIdx.x * Hh + t] = q;
    }
}

// ---------------- A2: reduce channel stats -> a2[h], c2[h] (log2e folded) ----
__global__ void k_stats(const float* __restrict__ gamma)
{
    int h = blockIdx.x, t = threadIdx.x;   // 256 threads
    __shared__ float rs[256], rq[256];
    float s = 0.f, q = 0.f;
    for (int b = t; b < NBLK_A; b += 256) {
        s += g_partS[b * Hh + h];
        q += g_partQ[b * Hh + h];
    }
    rs[t] = s; rq[t] = q;
    __syncthreads();
    for (int o = 128; o > 0; o >>= 1) {
        if (t < o) { rs[t] += rs[t + o]; rq[t] += rq[t + o]; }
        __syncthreads();
    }
    if (t == 0) {
        float mu  = rs[0] * (1.0f / (float)NNPAIR);
        float var = rq[0] * (1.0f / (float)NNPAIR) - mu * mu;
        float a2 = gamma[h] * rsqrtf(var + 1e-5f) * 1.4426950408889634f;
        g_a2[h] = a2;
        g_c2[h] = a2 * mu;
    }
}

// ---------------- B1: softmax-sum partials (reverse-i to catch passA L2 tail) -
__global__ void __launch_bounds__(256) k_sum()
{
    int b = blockIdx.x;
    int i = 767 - (b >> 2), qtr = b & 3;
    int tx = threadIdx.x & 15, ty = threadIdx.x >> 4;
    int h8 = tx * 8;
    __shared__ float sred[16 * 132];

    float4 aL = *(const float4*)&g_a2[h8];
    float4 aH = *(const float4*)&g_a2[h8 + 4];
    float4 cL = *(const float4*)&g_c2[h8];
    float4 cH = *(const float4*)&g_c2[h8 + 4];
    const uint4* rp = (const uint4*)(g_enew + (size_t)i * Nn * Hh);

    float s[8];
    #pragma unroll
    for (int u = 0; u < 8; u++) s[u] = 0.f;

    int j0 = qtr * 192 + ty;
    #pragma unroll 4
    for (int m = 0; m < 12; m++) {
        int j = j0 + m * 16;
        uint4 w = rp[j * 16 + tx];                       // evict-normal (k_gate reuses)
        float2 f0 = __half22float2(*reinterpret_cast<__half2*>(&w.x));
        float2 f1 = __half22float2(*reinterpret_cast<__half2*>(&w.y));
        float2 f2 = __half22float2(*reinterpret_cast<__half2*>(&w.z));
        float2 f3 = __half22float2(*reinterpret_cast<__half2*>(&w.w));
        s[0] += exp2f(fmaf(aL.x, f0.x, -cL.x));
        s[1] += exp2f(fmaf(aL.y, f0.y, -cL.y));
        s[2] += exp2f(fmaf(aL.z, f1.x, -cL.z));
        s[3] += exp2f(fmaf(aL.w, f1.y, -cL.w));
        s[4] += exp2f(fmaf(aH.x, f2.x, -cH.x));
        s[5] += exp2f(fmaf(aH.y, f2.y, -cH.y));
        s[6] += exp2f(fmaf(aH.z, f3.x, -cH.z));
        s[7] += exp2f(fmaf(aH.w, f3.y, -cH.w));
    }
    *(float4*)&sred[ty * 132 + h8]     = make_float4(s[0], s[1], s[2], s[3]);
    *(float4*)&sred[ty * 132 + h8 + 4] = make_float4(s[4], s[5], s[6], s[7]);
    __syncthreads();
    if (threadIdx.x < 128) {
        int h = threadIdx.x;
        float acc = 0.f;
        #pragma unroll
        for (int u = 0; u < 16; u++) acc += sred[u * 132 + h];
        g_Spart[(i * 4 + qtr) * Hh + h] = acc;
    }
}

// ---------------- B2: gates + e_next + numerator partials (forward-i) --------
__global__ void __launch_bounds__(256) k_gate(const float* __restrict__ e,
                                              float* __restrict__ eout)
{
    int b = blockIdx.x;
    int i = b >> 2, qtr = b & 3;
    int tx = threadIdx.x & 15, ty = threadIdx.x >> 4;
    int h8 = tx * 8;
    __shared__ float sred[16 * 132];

    float a2[8], c2p[8];
    #pragma unroll
    for (int u = 0; u < 8; u++) {
        int h = h8 + u;
        float S = ((g_Spart[(i * 4 + 0) * Hh + h] + g_Spart[(i * 4 + 1) * Hh + h])
                 + (g_Spart[(i * 4 + 2) * Hh + h] + g_Spart[(i * 4 + 3) * Hh + h]));
        a2[u]  = g_a2[h];
        c2p[u] = g_c2[h] + __log2f(S);
    }

    const uint4*  rp = (const uint4*)(g_enew + (size_t)i * Nn * Hh);
    const float4* ep = (const float4*)(e    + (size_t)i * Nn * Hh);
    float4*       op = (float4*)(eout + (size_t)i * Nn * Hh);

    float wacc[8];
    #pragma unroll
    for (int u = 0; u < 8; u++) wacc[u] = 0.f;

    int j0 = qtr * 192 + ty;
    #pragma unroll 4
    for (int m = 0; m < 12; m++) {
        int j = j0 + m * 16;
        uint4 w = __ldcs(&rp[j * 16 + tx]);              // last use of enew
        float4 evL = __ldcs(&ep[j * 32 + tx * 2]);
        float4 evH = __ldcs(&ep[j * 32 + tx * 2 + 1]);
        float4 vvL = *(const float4*)&g_vx2[j * Hh + h8];
        float4 vvH = *(const float4*)&g_vx2[j * Hh + h8 + 4];
        float2 f0 = __half22float2(*reinterpret_cast<__half2*>(&w.x));
        float2 f1 = __half22float2(*reinterpret_cast<__half2*>(&w.y));
        float2 f2 = __half22float2(*reinterpret_cast<__half2*>(&w.z));
        float2 f3 = __half22float2(*reinterpret_cast<__half2*>(&w.w));
        float g0 = exp2f(fmaf(a2[0], f0.x, -c2p[0]));
        float g1 = exp2f(fmaf(a2[1], f0.y, -c2p[1]));
        float g2 = exp2f(fmaf(a2[2], f1.x, -c2p[2]));
        float g3 = exp2f(fmaf(a2[3], f1.y, -c2p[3]));
        float g4 = exp2f(fmaf(a2[4], f2.x, -c2p[4]));
        float g5 = exp2f(fmaf(a2[5], f2.y, -c2p[5]));
        float g6 = exp2f(fmaf(a2[6], f3.x, -c2p[6]));
        float g7 = exp2f(fmaf(a2[7], f3.y, -c2p[7]));
        float4 oL, oH;
        oL.x = fmaf(g0, evL.x, evL.x);
        oL.y = fmaf(g1, evL.y, evL.y);
        oL.z = fmaf(g2, evL.z, evL.z);
        oL.w = fmaf(g3, evL.w, evL.w);
        oH.x = fmaf(g4, evH.x, evH.x);
        oH.y = fmaf(g5, evH.y, evH.y);
        oH.z = fmaf(g6, evH.z, evH.z);
        oH.w = fmaf(g7, evH.w, evH.w);
        __stcs(&op[j * 32 + tx * 2],     oL);
        __stcs(&op[j * 32 + tx * 2 + 1], oH);
        wacc[0] = fmaf(g0, vvL.x, wacc[0]);
        wacc[1] = fmaf(g1, vvL.y, wacc[1]);
        wacc[2] = fmaf(g2, vvL.z, wacc[2]);
        wacc[3] = fmaf(g3, vvL.w, wacc[3]);
        wacc[4] = fmaf(g4, vvH.x, wacc[4]);
        wacc[5] = fmaf(g5, vvH.y, wacc[5]);
        wacc[6] = fmaf(g6, vvH.z, wacc[6]);
        wacc[7] = fmaf(g7, vvH.w, wacc[7]);
    }
    *(float4*)&sred[ty * 132 + h8]     = make_float4(wacc[0], wacc[1], wacc[2], wacc[3]);
    *(float4*)&sred[ty * 132 + h8 + 4] = make_float4(wacc[4], wacc[5], wacc[6], wacc[7]);
    __syncthreads();
    if (threadIdx.x < 128) {
        int h = threadIdx.x;
        float acc = 0.f;
        #pragma unroll
        for (int u = 0; u < 16; u++) acc += sred[u * 132 + h];
        g_numpart[(i * 4 + qtr) * Hh + h] = acc;   // already normalized: sum(g*vx2)
    }
}

// ---------------- D: node BN + residual --------------------------------------
__global__ void k_node(const float* __restrict__ x,
                       const float* __restrict__ gamma,
                       const float* __restrict__ beta,
                       float* __restrict__ outx)
{
    int h = blockIdx.x, t = threadIdx.x;   // 256 threads
    __shared__ float vbuf[Nn];
    __shared__ float rs[256], rq[256];
    float s = 0.f, q = 0.f;
    for (int i = t; i < Nn; i += 256) {
        float num = ((g_numpart[(i * 4 + 0) * Hh + h] + g_numpart[(i * 4 + 1) * Hh + h])
                   + (g_numpart[(i * 4 + 2) * Hh + h] + g_numpart[(i * 4 + 3) * Hh + h]));
        float v = g_ux[i * Hh + h] + num;   // den = 1 (+1e-20), normalization folded
        vbuf[i] = v;
        s += v;
        q = fmaf(v, v, q);
    }
    rs[t] = s; rq[t] = q;
    __syncthreads();
    for (int o = 128; o > 0; o >>= 1) {
        if (t < o) { rs[t] += rs[t + o]; rq[t] += rq[t + o]; }
        __syncthreads();
    }
    float mu  = rs[0] * (1.0f / (float)Nn);
    float var = rq[0] * (1.0f / (float)Nn) - mu * mu;
    float scg = gamma[h] * rsqrtf(var + 1e-5f);
    float be  = beta[h];
    for (int i = t; i < Nn; i += 256) {
        float bn = fmaf(scg, vbuf[i] - mu, be);
        outx[i * Hh + h] = x[i * Hh + h] + fmaxf(bn, 0.f);
    }
}

// ---------------- launch ------------------------------------------------------
extern "C" void kernel_launch(void* const* d_in, const int* in_sizes, int n_in,
                              void* d_out, int out_size)
{
    const float* x     = (const float*)d_in[0];
    const float* e     = (const float*)d_in[1];
    const float* eU_w  = (const float*)d_in[2];
    const float* eU_b  = (const float*)d_in[3];
    const float* eV_w  = (const float*)d_in[4];
    const float* eV_b  = (const float*)d_in[5];
    const float* nU_w  = (const float*)d_in[6];
    const float* nU_b  = (const float*)d_in[7];
    const float* nV_w  = (const float*)d_in[8];
    const float* nV_b  = (const float*)d_in[9];
    const float* e_gamma = (const float*)d_in[10];
    // d_in[11] = e_beta: constant over the softmax axis -> cancels exactly
    const float* n_gamma = (const float*)d_in[12];
    const float* n_beta  = (const float*)d_in[13];
    (void)in_sizes; (void)n_in; (void)out_size;

    float* out_x = (float*)d_out;               // x_next: [768,128]
    float* out_e = out_x + Nn * Hh;             // e_next: [768,768,128]

    const int PASSA_SMEM = 2 * 8704 * 4;        // 69632 B dynamic
    static bool attr_done = false;
    if (!attr_done) {
        cudaFuncSetAttribute(k_passA, cudaFuncAttributeMaxDynamicSharedMemorySize,
                             PASSA_SMEM);
        attr_done = true;
    }

    // Linears split into 3 launches so k_passA lands in the ncu capture slot.
    k_linear1<<<Nn, Hh>>>(x, eV_w, eV_b, eU_w, 0);   // also converts eU_w -> fp16
    k_linear1<<<Nn, Hh>>>(x, nU_w, nU_b, eU_w, 1);
    k_linear1<<<Nn, Hh>>>(x, nV_w, nV_b, eU_w, 2);
    k_passA  <<<NBLK_A, 256, PASSA_SMEM>>>(e, eU_b);
    k_stats  <<<Hh, 256>>>(e_gamma);
    k_sum    <<<Nn * 4, 256>>>();
    k_gate   <<<Nn * 4, 256>>>(e, out_e);
    k_node   <<<Hh, 256>>>(x, n_gamma, n_beta, out_x);
}

// round 14
// speedup vs baseline: 1.1698x; 1.0174x over previous
#include <cuda_runtime.h>
#include <cuda_fp16.h>
#include <cstdint>

#define Nn 768
#define Hh 128
#define NNPAIR (768 * 768)          // 589824
#define NBLK_A (NNPAIR / 128)       // 4608

// ---------------- scratch (__device__ globals; no allocation allowed) -------
__device__ __align__(16) __half g_enew[589824ull * 128];   // 151 MB fp16 z
__device__ __align__(16) __half g_w16[Hh * Hh];            // eU_w in fp16
__device__ float g_partS[NBLK_A * Hh];
__device__ float g_partQ[NBLK_A * Hh];
__device__ float g_a2[Hh];                  // gamma * rsqrt(var+eps) * log2(e)
__device__ float g_c2[Hh];                  // a2 * mu
__device__ float g_vx  [Nn * Hh];           // x @ eV_w^T + eV_b
__device__ float g_ux  [Nn * Hh];           // x @ nU_w^T + nU_b
__device__ float g_vx2 [Nn * Hh];           // x @ nV_w^T + nV_b
__device__ float g_Spart[Nn * 4 * Hh];      // softmax-sum partials (4 j-quarters)
__device__ float g_numpart[Nn * 4 * Hh];    // normalized-gate numerator partials

// ---------------- helpers ----------------------------------------------------
__device__ __forceinline__ uint32_t pack_h2(float x, float y)
{
    __half2 h = __floats2half2_rn(x, y);
    return *reinterpret_cast<uint32_t*>(&h);
}
__device__ __forceinline__ void ldsm_x4(uint32_t addr, uint32_t& r0, uint32_t& r1,
                                        uint32_t& r2, uint32_t& r3)
{
    asm volatile("ldmatrix.sync.aligned.m8n8.x4.shared.b16 {%0,%1,%2,%3}, [%4];"
                 : "=r"(r0), "=r"(r1), "=r"(r2), "=r"(r3) : "r"(addr));
}
__device__ __forceinline__ void ldsm_x2(uint32_t addr, uint32_t& r0, uint32_t& r1)
{
    asm volatile("ldmatrix.sync.aligned.m8n8.x2.shared.b16 {%0,%1}, [%2];"
                 : "=r"(r0), "=r"(r1) : "r"(addr));
}
__device__ __forceinline__ void stsm_x2(uint32_t addr, uint32_t v0, uint32_t v1)
{
    asm volatile("stmatrix.sync.aligned.m8n8.x2.shared.b16 [%0], {%1,%2};"
                 :: "r"(addr), "r"(v0), "r"(v1) : "memory");
}
__device__ __forceinline__ void mma16816(float* d, uint32_t a0, uint32_t a1,
                                         uint32_t a2, uint32_t a3,
                                         uint32_t b0, uint32_t b1)
{
    asm volatile(
        "mma.sync.aligned.m16n8k16.row.col.f32.f16.f16.f32 "
        "{%0,%1,%2,%3}, {%4,%5,%6,%7}, {%8,%9}, {%0,%1,%2,%3};"
        : "+f"(d[0]), "+f"(d[1]), "+f"(d[2]), "+f"(d[3])
        : "r"(a0), "r"(a1), "r"(a2), "r"(a3), "r"(b0), "r"(b1));
}

// ---------------- kernel 0: one node linear (3x); which==0 also converts W ---
__global__ void k_linear1(const float* __restrict__ x,
                          const float* __restrict__ W, const float* __restrict__ b,
                          const float* __restrict__ Wconv, int which)
{
    __shared__ float xs[Hh];
    __shared__ float Ws[32 * 129];
    int i = blockIdx.x, t = threadIdx.x;
    xs[t] = x[i * Hh + t];

    if (which == 0 && i < Hh)
        g_w16[i * Hh + t] = __float2half_rn(Wconv[i * Hh + t]);

    float* out = (which == 0) ? g_vx : (which == 1) ? g_ux : g_vx2;

    int warp = t >> 5, lane = t & 31;
    float acc = 0.f;
    for (int kb = 0; kb < 4; kb++) {
        __syncthreads();
        #pragma unroll
        for (int m = 0; m < 32; m++) {
            int h = m * 4 + warp;
            Ws[lane * 129 + h] = W[h * Hh + kb * 32 + lane];
        }
        __syncthreads();
        #pragma unroll
        for (int kk = 0; kk < 32; kk++)
            acc = fmaf(xs[kb * 32 + kk], Ws[kk * 129 + t], acc);
    }
    out[i * Hh + t] = acc + b[t];
}

// ---------------- pass A: fp16 HMMA GEMM, 64x64 warp tiles (4 warps) ---------
extern __shared__ uint32_t dynbuf[];

__global__ void __launch_bounds__(128, 2) k_passA(const float* __restrict__ e,
                                                  const float* __restrict__ bias)
{
    __shared__ float sPS[2 * 128], sPQ[2 * 128];   // per-wm channel partials

    int t = threadIdx.x;
    int warp = t >> 5, lane = t & 31;
    int wm = warp & 1;                     // rows wm*64
    int wn = warp >> 1;                    // cols wn*64
    int p0 = blockIdx.x * 128;
    int i0 = p0 / Nn;                      // constant per block (128 | 768)
    int jbase = p0 - i0 * Nn;

    uint32_t* Awords = dynbuf;             // [128][68] words (pitch 272 B)
    uint32_t* Wwords = dynbuf + 8704;
    uint32_t sbase = (uint32_t)__cvta_generic_to_shared(Awords);
    uint32_t Wbase = (uint32_t)__cvta_generic_to_shared(Wwords);

    // stage A (e tile): 4096 float4, 32 per thread
    #pragma unroll
    for (int m = 0; m < 32; m++) {
        int idx = m * 128 + t;
        int r = idx >> 5, q = idx & 31;
        float4 v = __ldcs((const float4*)&e[(size_t)(p0 + r) * Hh + q * 4]);
        *(uint2*)&Awords[r * 68 + q * 2] = make_uint2(pack_h2(v.x, v.y), pack_h2(v.z, v.w));
    }
    // stage W: fp16 copy, 2048 uint4, 16 per thread
    #pragma unroll
    for (int m = 0; m < 16; m++) {
        int idx = m * 128 + t;
        int r = idx >> 4, c = idx & 15;
        uint4 v = *(const uint4*)&g_w16[r * Hh + c * 8];
        *(uint4*)&Wwords[r * 68 + c * 4] = v;
    }
    __syncthreads();

    int a_r = lane & 15;
    int a_c16 = ((lane >> 4) & 1) * 8;
    int b_r = lane & 7;
    int b_c16 = ((lane >> 3) & 1) * 8;

    float acc[4][8][4];
    #pragma unroll
    for (int mi = 0; mi < 4; mi++)
        #pragma unroll
        for (int ni = 0; ni < 8; ni++)
            #pragma unroll
            for (int q = 0; q < 4; q++) acc[mi][ni][q] = 0.f;

    #pragma unroll
    for (int ks = 0; ks < 8; ks++) {
        uint32_t bfr[8][2];
        #pragma unroll
        for (int ni = 0; ni < 8; ni++) {
            int brow = wn * 64 + ni * 8 + b_r;
            uint32_t addr = Wbase + (uint32_t)(brow * 272 + (ks * 16 + b_c16) * 2);
            ldsm_x2(addr, bfr[ni][0], bfr[ni][1]);
        }
        #pragma unroll
        for (int mi = 0; mi < 4; mi++) {
            int arow = wm * 64 + mi * 16 + a_r;
            uint32_t addr = sbase + (uint32_t)(arow * 272 + (ks * 16 + a_c16) * 2);
            uint32_t a0, a1, a2, a3;
            ldsm_x4(addr, a0, a1, a2, a3);
            #pragma unroll
            for (int ni = 0; ni < 8; ni++)
                mma16816(acc[mi][ni], a0, a1, a2, a3, bfr[ni][0], bfr[ni][1]);
        }
    }
    __syncthreads();                       // smem reads done; reuse A region as out

    // epilogue: val = (acc + bias)*(vxi + vxj); STSM tile store; reg/shfl partials
    uint32_t* Osm = Awords;
    int strow = wm * 64 + (lane & 7) + ((lane >> 3) & 1) * 8;  // + mi*16 below
    #pragma unroll
    for (int ni = 0; ni < 8; ni++) {
        int col = wn * 64 + ni * 8 + (lane & 3) * 2;
        float2 bb = *(const float2*)&bias[col];
        float2 vi = *(const float2*)&g_vx[i0 * Hh + col];
        float sc0 = 0.f, sc1 = 0.f, qc0 = 0.f, qc1 = 0.f;
        #pragma unroll
        for (int mi = 0; mi < 4; mi++) {
            int r1 = wm * 64 + mi * 16 + (lane >> 2);
            int r2 = r1 + 8;
            float2 vj1 = *(const float2*)&g_vx[(jbase + r1) * Hh + col];
            float2 vj2 = *(const float2*)&g_vx[(jbase + r2) * Hh + col];
            float* a = acc[mi][ni];
            float v00 = (a[0] + bb.x) * (vi.x + vj1.x);
            float v01 = (a[1] + bb.y) * (vi.y + vj1.y);
            float v10 = (a[2] + bb.x) * (vi.x + vj2.x);
            float v11 = (a[3] + bb.y) * (vi.y + vj2.y);
            uint32_t zA = pack_h2(v00, v01);
            uint32_t zB = pack_h2(v10, v11);
            float2 za = __half22float2(*reinterpret_cast<__half2*>(&zA));
            float2 zb = __half22float2(*reinterpret_cast<__half2*>(&zB));
            sc0 += za.x + zb.x;
            sc1 += za.y + zb.y;
            qc0 += za.x * za.x + zb.x * zb.x;
            qc1 += za.y * za.y + zb.y * zb.y;
            uint32_t saddr = sbase +
                (uint32_t)(((strow + mi * 16) * 68 + wn * 32 + ni * 4) * 4);
            stsm_x2(saddr, zA, zB);
        }
        #pragma unroll
        for (int o = 4; o <= 16; o <<= 1) {
            sc0 += __shfl_xor_sync(0xffffffffu, sc0, o);
            sc1 += __shfl_xor_sync(0xffffffffu, sc1, o);
            qc0 += __shfl_xor_sync(0xffffffffu, qc0, o);
            qc1 += __shfl_xor_sync(0xffffffffu, qc1, o);
        }
        // wm slice partials: two warps with same wm write disjoint col halves
        if (lane < 4) {
            sPS[wm * 128 + col]     = sc0;
            sPS[wm * 128 + col + 1] = sc1;
            sPQ[wm * 128 + col]     = qc0;
            sPQ[wm * 128 + col + 1] = qc1;
        }
    }
    __syncthreads();

    // coalesced STG.128 global write: 128 rows x 16 uint4; 16 per thread
    uint32_t* gout = (uint32_t*)g_enew;
    #pragma unroll
    for (int m = 0; m < 16; m++) {
        int idx = m * 128 + t;
        int r = idx >> 4, w4 = idx & 15;
        uint4 v = *(uint4*)&Osm[r * 68 + w4 * 4];
        *(uint4*)&gout[(size_t)(p0 + r) * 64 + w4 * 4] = v;
    }

    // final per-channel partials (2 wm slices, fixed order)
    if (t < 128) {
        g_partS[blockIdx.x * Hh + t] = sPS[t] + sPS[128 + t];
        g_partQ[blockIdx.x * Hh + t] = sPQ[t] + sPQ[128 + t];
    }
}

// ---------------- A2: reduce channel stats -> a2[h], c2[h] (log2e folded) ----
__global__ void k_stats(const float* __restrict__ gamma)
{
    int h = blockIdx.x, t = threadIdx.x;   // 256 threads
    __shared__ float rs[256], rq[256];
    float s = 0.f, q = 0.f;
    for (int b = t; b < NBLK_A; b += 256) {
        s += g_partS[b * Hh + h];
        q += g_partQ[b * Hh + h];
    }
    rs[t] = s; rq[t] = q;
    __syncthreads();
    for (int o = 128; o > 0; o >>= 1) {
        if (t < o) { rs[t] += rs[t + o]; rq[t] += rq[t + o]; }
        __syncthreads();
    }
    if (t == 0) {
        float mu  = rs[0] * (1.0f / (float)NNPAIR);
        float var = rq[0] * (1.0f / (float)NNPAIR) - mu * mu;
        float a2 = gamma[h] * rsqrtf(var + 1e-5f) * 1.4426950408889634f;
        g_a2[h] = a2;
        g_c2[h] = a2 * mu;
    }
}

// ---------------- B1: softmax-sum partials (reverse-i to catch passA L2 tail) -
__global__ void __launch_bounds__(256) k_sum()
{
    int b = blockIdx.x;
    int i = 767 - (b >> 2), qtr = b & 3;
    int tx = threadIdx.x & 15, ty = threadIdx.x >> 4;
    int h8 = tx * 8;
    __shared__ float sred[16 * 132];

    float4 aL = *(const float4*)&g_a2[h8];
    float4 aH = *(const float4*)&g_a2[h8 + 4];
    float4 cL = *(const float4*)&g_c2[h8];
    float4 cH = *(const float4*)&g_c2[h8 + 4];
    const uint4* rp = (const uint4*)(g_enew + (size_t)i * Nn * Hh);

    float s[8];
    #pragma unroll
    for (int u = 0; u < 8; u++) s[u] = 0.f;

    int j0 = qtr * 192 + ty;
    #pragma unroll 4
    for (int m = 0; m < 12; m++) {
        int j = j0 + m * 16;
        uint4 w = rp[j * 16 + tx];                       // evict-normal (k_gate reuses)
        float2 f0 = __half22float2(*reinterpret_cast<__half2*>(&w.x));
        float2 f1 = __half22float2(*reinterpret_cast<__half2*>(&w.y));
        float2 f2 = __half22float2(*reinterpret_cast<__half2*>(&w.z));
        float2 f3 = __half22float2(*reinterpret_cast<__half2*>(&w.w));
        s[0] += exp2f(fmaf(aL.x, f0.x, -cL.x));
        s[1] += exp2f(fmaf(aL.y, f0.y, -cL.y));
        s[2] += exp2f(fmaf(aL.z, f1.x, -cL.z));
        s[3] += exp2f(fmaf(aL.w, f1.y, -cL.w));
        s[4] += exp2f(fmaf(aH.x, f2.x, -cH.x));
        s[5] += exp2f(fmaf(aH.y, f2.y, -cH.y));
        s[6] += exp2f(fmaf(aH.z, f3.x, -cH.z));
        s[7] += exp2f(fmaf(aH.w, f3.y, -cH.w));
    }
    *(float4*)&sred[ty * 132 + h8]     = make_float4(s[0], s[1], s[2], s[3]);
    *(float4*)&sred[ty * 132 + h8 + 4] = make_float4(s[4], s[5], s[6], s[7]);
    __syncthreads();
    if (threadIdx.x < 128) {
        int h = threadIdx.x;
        float acc = 0.f;
        #pragma unroll
        for (int u = 0; u < 16; u++) acc += sred[u * 132 + h];
        g_Spart[(i * 4 + qtr) * Hh + h] = acc;
    }
}

// ---------------- B2: gates + e_next + numerator partials (forward-i) --------
__global__ void __launch_bounds__(256) k_gate(const float* __restrict__ e,
                                              float* __restrict__ eout)
{
    int b = blockIdx.x;
    int i = b >> 2, qtr = b & 3;
    int tx = threadIdx.x & 15, ty = threadIdx.x >> 4;
    int h8 = tx * 8;
    __shared__ float sred[16 * 132];

    float a2[8], c2p[8];
    #pragma unroll
    for (int u = 0; u < 8; u++) {
        int h = h8 + u;
        float S = ((g_Spart[(i * 4 + 0) * Hh + h] + g_Spart[(i * 4 + 1) * Hh + h])
                 + (g_Spart[(i * 4 + 2) * Hh + h] + g_Spart[(i * 4 + 3) * Hh + h]));
        a2[u]  = g_a2[h];
        c2p[u] = g_c2[h] + __log2f(S);
    }

    const uint4*  rp = (const uint4*)(g_enew + (size_t)i * Nn * Hh);
    const float4* ep = (const float4*)(e    + (size_t)i * Nn * Hh);
    float4*       op = (float4*)(eout + (size_t)i * Nn * Hh);

    float wacc[8];
    #pragma unroll
    for (int u = 0; u < 8; u++) wacc[u] = 0.f;

    int j0 = qtr * 192 + ty;
    #pragma unroll 4
    for (int m = 0; m < 12; m++) {
        int j = j0 + m * 16;
        uint4 w = __ldcs(&rp[j * 16 + tx]);              // last use of enew
        float4 evL = __ldcs(&ep[j * 32 + tx * 2]);
        float4 evH = __ldcs(&ep[j * 32 + tx * 2 + 1]);
        float4 vvL = *(const float4*)&g_vx2[j * Hh + h8];
        float4 vvH = *(const float4*)&g_vx2[j * Hh + h8 + 4];
        float2 f0 = __half22float2(*reinterpret_cast<__half2*>(&w.x));
        float2 f1 = __half22float2(*reinterpret_cast<__half2*>(&w.y));
        float2 f2 = __half22float2(*reinterpret_cast<__half2*>(&w.z));
        float2 f3 = __half22float2(*reinterpret_cast<__half2*>(&w.w));
        float g0 = exp2f(fmaf(a2[0], f0.x, -c2p[0]));
        float g1 = exp2f(fmaf(a2[1], f0.y, -c2p[1]));
        float g2 = exp2f(fmaf(a2[2], f1.x, -c2p[2]));
        float g3 = exp2f(fmaf(a2[3], f1.y, -c2p[3]));
        float g4 = exp2f(fmaf(a2[4], f2.x, -c2p[4]));
        float g5 = exp2f(fmaf(a2[5], f2.y, -c2p[5]));
        float g6 = exp2f(fmaf(a2[6], f3.x, -c2p[6]));
        float g7 = exp2f(fmaf(a2[7], f3.y, -c2p[7]));
        float4 oL, oH;
        oL.x = fmaf(g0, evL.x, evL.x);
        oL.y = fmaf(g1, evL.y, evL.y);
        oL.z = fmaf(g2, evL.z, evL.z);
        oL.w = fmaf(g3, evL.w, evL.w);
        oH.x = fmaf(g4, evH.x, evH.x);
        oH.y = fmaf(g5, evH.y, evH.y);
        oH.z = fmaf(g6, evH.z, evH.z);
        oH.w = fmaf(g7, evH.w, evH.w);
        __stcs(&op[j * 32 + tx * 2],     oL);
        __stcs(&op[j * 32 + tx * 2 + 1], oH);
        wacc[0] = fmaf(g0, vvL.x, wacc[0]);
        wacc[1] = fmaf(g1, vvL.y, wacc[1]);
        wacc[2] = fmaf(g2, vvL.z, wacc[2]);
        wacc[3] = fmaf(g3, vvL.w, wacc[3]);
        wacc[4] = fmaf(g4, vvH.x, wacc[4]);
        wacc[5] = fmaf(g5, vvH.y, wacc[5]);
        wacc[6] = fmaf(g6, vvH.z, wacc[6]);
        wacc[7] = fmaf(g7, vvH.w, wacc[7]);
    }
    *(float4*)&sred[ty * 132 + h8]     = make_float4(wacc[0], wacc[1], wacc[2], wacc[3]);
    *(float4*)&sred[ty * 132 + h8 + 4] = make_float4(wacc[4], wacc[5], wacc[6], wacc[7]);
    __syncthreads();
    if (threadIdx.x < 128) {
        int h = threadIdx.x;
        float acc = 0.f;
        #pragma unroll
        for (int u = 0; u < 16; u++) acc += sred[u * 132 + h];
        g_numpart[(i * 4 + qtr) * Hh + h] = acc;   // already normalized: sum(g*vx2)
    }
}

// ---------------- D: node BN + residual --------------------------------------
__global__ void k_node(const float* __restrict__ x,
                       const float* __restrict__ gamma,
                       const float* __restrict__ beta,
                       float* __restrict__ outx)
{
    int h = blockIdx.x, t = threadIdx.x;   // 256 threads
    __shared__ float vbuf[Nn];
    __shared__ float rs[256], rq[256];
    float s = 0.f, q = 0.f;
    for (int i = t; i < Nn; i += 256) {
        float num = ((g_numpart[(i * 4 + 0) * Hh + h] + g_numpart[(i * 4 + 1) * Hh + h])
                   + (g_numpart[(i * 4 + 2) * Hh + h] + g_numpart[(i * 4 + 3) * Hh + h]));
        float v = g_ux[i * Hh + h] + num;   // den = 1 (+1e-20), normalization folded
        vbuf[i] = v;
        s += v;
        q = fmaf(v, v, q);
    }
    rs[t] = s; rq[t] = q;
    __syncthreads();
    for (int o = 128; o > 0; o >>= 1) {
        if (t < o) { rs[t] += rs[t + o]; rq[t] += rq[t + o]; }
        __syncthreads();
    }
    float mu  = rs[0] * (1.0f / (float)Nn);
    float var = rq[0] * (1.0f / (float)Nn) - mu * mu;
    float scg = gamma[h] * rsqrtf(var + 1e-5f);
    float be  = beta[h];
    for (int i = t; i < Nn; i += 256) {
        float bn = fmaf(scg, vbuf[i] - mu, be);
        outx[i * Hh + h] = x[i * Hh + h] + fmaxf(bn, 0.f);
    }
}

// ---------------- launch ------------------------------------------------------
extern "C" void kernel_launch(void* const* d_in, const int* in_sizes, int n_in,
                              void* d_out, int out_size)
{
    const float* x     = (const float*)d_in[0];
    const float* e     = (const float*)d_in[1];
    const float* eU_w  = (const float*)d_in[2];
    const float* eU_b  = (const float*)d_in[3];
    const float* eV_w  = (const float*)d_in[4];
    const float* eV_b  = (const float*)d_in[5];
    const float* nU_w  = (const float*)d_in[6];
    const float* nU_b  = (const float*)d_in[7];
    const float* nV_w  = (const float*)d_in[8];
    const float* nV_b  = (const float*)d_in[9];
    const float* e_gamma = (const float*)d_in[10];
    // d_in[11] = e_beta: constant over the softmax axis -> cancels exactly
    const float* n_gamma = (const float*)d_in[12];
    const float* n_beta  = (const float*)d_in[13];
    (void)in_sizes; (void)n_in; (void)out_size;

    float* out_x = (float*)d_out;               // x_next: [768,128]
    float* out_e = out_x + Nn * Hh;             // e_next: [768,768,128]

    const int PASSA_SMEM = 2 * 8704 * 4;        // 69632 B dynamic
    static bool attr_done = false;
    if (!attr_done) {
        cudaFuncSetAttribute(k_passA, cudaFuncAttributeMaxDynamicSharedMemorySize,
                             PASSA_SMEM);
        attr_done = true;
    }

    // Linears split into 3 launches so k_passA lands in the ncu capture slot.
    k_linear1<<<Nn, Hh>>>(x, eV_w, eV_b, eU_w, 0);   // also converts eU_w -> fp16
    k_linear1<<<Nn, Hh>>>(x, nU_w, nU_b, eU_w, 1);
    k_linear1<<<Nn, Hh>>>(x, nV_w, nV_b, eU_w, 2);
    k_passA  <<<NBLK_A, 128, PASSA_SMEM>>>(e, eU_b);
    k_stats  <<<Hh, 256>>>(e_gamma);
    k_sum    <<<Nn * 4, 256>>>();
    k_gate   <<<Nn * 4, 256>>>(e, out_e);
    k_node   <<<Hh, 256>>>(x, n_gamma, n_beta, out_x);
}